// round 13
// baseline (speedup 1.0000x reference)
#include <cuda_runtime.h>
#include <cuda_bf16.h>
#include <math.h>
#include <stdint.h>

#define NH   16
#define DH   64
#define SEQ  2048
#define BATCH 2
#define DM   1024
#define MROWS (BATCH*SEQ)   // 4096

__device__ __forceinline__ uint32_t smem_u32(const void* p) {
    uint32_t a;
    asm("{ .reg .u64 t; cvta.to.shared.u64 t, %1; cvt.u32.u64 %0, t; }"
        : "=r"(a) : "l"(p));
    return a;
}
__device__ __forceinline__ void cpa16(uint32_t s, const void* g) {
    asm volatile("cp.async.cg.shared.global [%0], [%1], 16;" :: "r"(s), "l"(g));
}
__device__ __forceinline__ void ldsm4(uint32_t r[4], uint32_t a) {
    asm volatile("ldmatrix.sync.aligned.m8n8.x4.shared.b16 {%0,%1,%2,%3}, [%4];"
                 : "=r"(r[0]), "=r"(r[1]), "=r"(r[2]), "=r"(r[3]) : "r"(a));
}
__device__ __forceinline__ void mma16816(float c[4], const uint32_t a[4],
                                         const uint32_t b0, const uint32_t b1) {
    asm volatile("mma.sync.aligned.m16n8k16.row.col.f32.bf16.bf16.f32 "
        "{%0,%1,%2,%3}, {%4,%5,%6,%7}, {%8,%9}, {%0,%1,%2,%3};"
        : "+f"(c[0]), "+f"(c[1]), "+f"(c[2]), "+f"(c[3])
        : "r"(a[0]), "r"(a[1]), "r"(a[2]), "r"(a[3]), "r"(b0), "r"(b1));
}
__device__ __forceinline__ uint32_t cvt2(float x, float y) {
    uint32_t r; asm("cvt.rn.bf16x2.f32 %0, %1, %2;" : "=r"(r) : "f"(y), "f"(x));
    return r;
}
__device__ __forceinline__ void bsplit(uint32_t &hi, uint32_t &lo, float x, float y) {
    uint32_t h = cvt2(x, y);
    float xr = x - __uint_as_float(h << 16);
    float yr = y - __uint_as_float(h & 0xffff0000u);
    hi = h; lo = cvt2(xr, yr);
}

// ---------------- scratch (device globals; no allocations allowed) ----------
__device__ float g_bias[NH*4096];                      // [h][rel+2047]
__device__ __nv_bfloat16 g_xh[(size_t)MROWS*DM];       // X hi
__device__ __nv_bfloat16 g_xl[(size_t)MROWS*DM];       // X lo
__device__ __nv_bfloat16 g_oh[(size_t)MROWS*DM];       // attn-out hi
__device__ __nv_bfloat16 g_ol[(size_t)MROWS*DM];       // attn-out lo
__device__ __nv_bfloat16 g_wth[4*(size_t)DM*DM];       // W^T hi [w][n][k]
__device__ __nv_bfloat16 g_wtl[4*(size_t)DM*DM];       // W^T lo
__device__ __nv_bfloat16 g_qh[(size_t)BATCH*NH*SEQ*DH];  // Q hi [b,h,s,d]
__device__ __nv_bfloat16 g_ql[(size_t)BATCH*NH*SEQ*DH];
__device__ __nv_bfloat16 g_kh[(size_t)BATCH*NH*SEQ*DH];  // K hi [b,h,s,d]
__device__ __nv_bfloat16 g_kl[(size_t)BATCH*NH*SEQ*DH];
__device__ __nv_bfloat16 g_vh[(size_t)BATCH*NH*DH*SEQ];  // V hi [b,h,d,s]
__device__ __nv_bfloat16 g_vl[(size_t)BATCH*NH*DH*SEQ];

// ---------------- relative-position bias table ------------------------------
__global__ void bias_kernel(const float* __restrict__ rel_emb) {
    int idx = blockIdx.x * blockDim.x + threadIdx.x;   // 0..4094
    if (idx >= 4095) return;
    int rel = idx - 2047;
    int bucket = (rel > 0) ? 16 : 0;
    int r = abs(rel);
    int bval;
    if (r < 8) bval = r;
    else {
        float v = logf((float)r / 8.0f) / 2.772588722239781f * 8.0f;
        bval = min(8 + (int)v, 15);
    }
    bucket += bval;
#pragma unroll
    for (int h = 0; h < NH; h++)
        g_bias[h*4096 + idx] = rel_emb[bucket*NH + h];
}

// ---------------- fp32 -> bf16 hi/lo split of X -----------------------------
__global__ void conv_split(const float4* __restrict__ src) {
    int i = blockIdx.x * blockDim.x + threadIdx.x;    // 1048576
    float4 v = src[i];
    uint32_t h0, l0, h1, l1;
    bsplit(h0, l0, v.x, v.y);
    bsplit(h1, l1, v.z, v.w);
    ((uint32_t*)g_xh)[2*i] = h0; ((uint32_t*)g_xh)[2*i+1] = h1;
    ((uint32_t*)g_xl)[2*i] = l0; ((uint32_t*)g_xl)[2*i+1] = l1;
}

// ---------------- weight transpose + split: W[K][N] -> W^T[N][K] bf16 -------
__global__ void conv_wT(const float* __restrict__ W0, const float* __restrict__ W1,
                        const float* __restrict__ W2, const float* __restrict__ W3) {
    __shared__ float t[32][33];
    int z = blockIdx.z;
    const float* W = (z == 0) ? W0 : (z == 1) ? W1 : (z == 2) ? W2 : W3;
    __nv_bfloat16* oh = g_wth + (size_t)z*DM*DM;
    __nv_bfloat16* ol = g_wtl + (size_t)z*DM*DM;
    int k0 = blockIdx.y*32, n0 = blockIdx.x*32;
    int tx = threadIdx.x, ty = threadIdx.y;   // (32, 8)
#pragma unroll
    for (int j = 0; j < 4; j++)
        t[tx][ty + 8*j] = W[(size_t)(k0 + ty + 8*j)*DM + n0 + tx];
    __syncthreads();
#pragma unroll
    for (int j = 0; j < 4; j++) {
        float v = t[ty + 8*j][tx];
        __nv_bfloat16 h = __float2bfloat16(v);
        __nv_bfloat16 l = __float2bfloat16(v - __bfloat162float(h));
        size_t o = (size_t)(n0 + ty + 8*j)*DM + k0 + tx;
        oh[o] = h; ol[o] = l;
    }
}

// ---------------- warp-MMA GEMM (HMMA bf16, 3-pass hi/lo) -------------------
// CTA tile 128x128, 8 warps of 64x32, K chunk 32.
// 3-stage single-barrier cp.async pipeline; pad-free XOR-swizzled 64B rows.
#define AST    32768            // stage: 4 arrays x 128 rows x 64B
#define OFF_AH 0
#define OFF_AL 8192
#define OFF_BH 16384
#define OFF_BL 24576
#define G_SMEM (3*AST)          // 98304; epilogue needs 128*136*4=69632 <= this

__global__ __launch_bounds__(256) void gemm_mma(int fused, float* __restrict__ Cext) {
    extern __shared__ __align__(16) char sm[];
    uint32_t sb = smem_u32(sm);
    const int tid = threadIdx.x, lane = tid & 31, w = tid >> 5;
    const int wm = w >> 2, wn = w & 3;
    const int by = blockIdx.y;

    int wsel, bxx, cmode;
    if (fused) { wsel = blockIdx.x >> 3; bxx = blockIdx.x & 7; cmode = wsel; }
    else       { wsel = 3; bxx = blockIdx.x; cmode = 3; }

    const __nv_bfloat16* Ah = (fused ? g_xh : g_oh) + (size_t)(by*128)*DM;
    const __nv_bfloat16* Al = (fused ? g_xl : g_ol) + (size_t)(by*128)*DM;
    const __nv_bfloat16* Bh = g_wth + (size_t)wsel*DM*DM + (size_t)(bxx*128)*DM;
    const __nv_bfloat16* Bl = g_wtl + (size_t)wsel*DM*DM + (size_t)(bxx*128)*DM;

    const int lr  = tid >> 2;       // 0..63
    const int blk = tid & 3;        // 16B block within 64B row

    float acc[4][4][4];
#pragma unroll
    for (int mt = 0; mt < 4; mt++)
#pragma unroll
        for (int nt = 0; nt < 4; nt++)
#pragma unroll
            for (int e = 0; e < 4; e++) acc[mt][nt][e] = 0.f;

    uint32_t aRow[4], aXr[4], bRow[2], bXr[2];
#pragma unroll
    for (int mt = 0; mt < 4; mt++) {
        int row = wm*64 + mt*16 + (lane & 15);
        aRow[mt] = (uint32_t)row * 64;
        aXr[mt]  = (uint32_t)((row >> 1) & 3);
    }
    {
        int br0 = wn*32 + (lane & 7) + ((lane >> 4) & 1) * 8;
        int br1 = br0 + 16;
        bRow[0] = (uint32_t)br0 * 64; bXr[0] = (uint32_t)((br0 >> 1) & 3);
        bRow[1] = (uint32_t)br1 * 64; bXr[1] = (uint32_t)((br1 >> 1) & 3);
    }
    const uint32_t cbiA = (uint32_t)(lane >> 4);
    const uint32_t cbiB = (uint32_t)((lane >> 3) & 1);

#define ISSUE(c) do {                                                          \
    uint32_t stb_ = sb + ((c) % 3) * AST;                                      \
    int kofs_ = (c)*32 + blk*8;                                                \
    _Pragma("unroll")                                                          \
    for (int half = 0; half < 2; half++) {                                     \
        int r_ = lr + half*64;                                                 \
        uint32_t so_ = (uint32_t)r_*64 + (((uint32_t)blk ^ ((r_>>1)&3))*16);   \
        size_t go_ = (size_t)r_*DM + kofs_;                                    \
        cpa16(stb_ + OFF_AH + so_, Ah + go_);                                  \
        cpa16(stb_ + OFF_AL + so_, Al + go_);                                  \
        cpa16(stb_ + OFF_BH + so_, Bh + go_);                                  \
        cpa16(stb_ + OFF_BL + so_, Bl + go_);                                  \
    }                                                                          \
    asm volatile("cp.async.commit_group;" ::: "memory");                       \
} while (0)

    ISSUE(0);
    ISSUE(1);

    for (int c = 0; c < 32; c++) {
        if (c < 31) asm volatile("cp.async.wait_group 1;" ::: "memory");
        else        asm volatile("cp.async.wait_group 0;" ::: "memory");
        __syncthreads();                 // single barrier: data visible + old stage free
        if (c < 30) ISSUE(c + 2);        // writes stage (c-1)%3, safe after barrier

        uint32_t stb = sb + (c % 3) * AST;
#pragma unroll
        for (int s = 0; s < 2; s++) {
            uint32_t ah[4][4], al[4][4], bh[2][4], bl[2][4];
            uint32_t bA = 2*s + cbiA;
            uint32_t bB = 2*s + cbiB;
#pragma unroll
            for (int mt = 0; mt < 4; mt++) {
                uint32_t off = aRow[mt] + ((bA ^ aXr[mt]) << 4);
                ldsm4(ah[mt], stb + OFF_AH + off);
                ldsm4(al[mt], stb + OFF_AL + off);
            }
#pragma unroll
            for (int p = 0; p < 2; p++) {
                uint32_t off = bRow[p] + ((bB ^ bXr[p]) << 4);
                ldsm4(bh[p], stb + OFF_BH + off);
                ldsm4(bl[p], stb + OFF_BL + off);
            }
            // pass 1: a_hi * b_hi
#pragma unroll
            for (int mt = 0; mt < 4; mt++)
#pragma unroll
                for (int nt = 0; nt < 4; nt++) {
                    const uint32_t* bth = bh[nt >> 1] + (nt & 1) * 2;
                    mma16816(acc[mt][nt], ah[mt], bth[0], bth[1]);
                }
            // pass 2: a_hi * b_lo
#pragma unroll
            for (int mt = 0; mt < 4; mt++)
#pragma unroll
                for (int nt = 0; nt < 4; nt++) {
                    const uint32_t* btl = bl[nt >> 1] + (nt & 1) * 2;
                    mma16816(acc[mt][nt], ah[mt], btl[0], btl[1]);
                }
            // pass 3: a_lo * b_hi
#pragma unroll
            for (int mt = 0; mt < 4; mt++)
#pragma unroll
                for (int nt = 0; nt < 4; nt++) {
                    const uint32_t* bth = bh[nt >> 1] + (nt & 1) * 2;
                    mma16816(acc[mt][nt], al[mt], bth[0], bth[1]);
                }
        }
    }
    __syncthreads();   // protect smem before epilogue staging

    // ---- epilogue: stage C tile through smem (reuse pipeline buffers)
    float (*Cs)[136] = (float (*)[136])sm;
#pragma unroll
    for (int mt = 0; mt < 4; mt++)
#pragma unroll
        for (int nt = 0; nt < 4; nt++) {
            int row = wm*64 + mt*16 + (lane >> 2);
            int col = wn*32 + nt*8 + 2*(lane & 3);
            Cs[row    ][col] = acc[mt][nt][0]; Cs[row    ][col+1] = acc[mt][nt][1];
            Cs[row + 8][col] = acc[mt][nt][2]; Cs[row + 8][col+1] = acc[mt][nt][3];
        }
    __syncthreads();

    int b = by >> 4;
    if (cmode == 3) {
        int mr = tid >> 1, half = tid & 1;
        const float* src = &Cs[mr][half*64];
        float* dst = Cext + (size_t)(by*128 + mr)*DM + bxx*128 + half*64;
#pragma unroll
        for (int j = 0; j < 16; j++)
            ((float4*)dst)[j] = ((const float4*)src)[j];
    } else if (cmode <= 1) {
        int mr = tid >> 1, half = tid & 1;
        int hh = bxx*2 + half;
        int s  = (by & 15)*128 + mr;
        __nv_bfloat16* DST_H = cmode ? g_kh : g_qh;
        __nv_bfloat16* DST_L = cmode ? g_kl : g_ql;
        size_t base = ((size_t)(b*NH + hh)*SEQ + s)*DH;
        const float* src = &Cs[mr][half*64];
#pragma unroll
        for (int j8 = 0; j8 < 8; j8++) {
            uint32_t hv[4], lv[4];
#pragma unroll
            for (int e = 0; e < 4; e++)
                bsplit(hv[e], lv[e], src[j8*8 + 2*e], src[j8*8 + 2*e + 1]);
            *(uint4*)(DST_H + base + j8*8) = make_uint4(hv[0], hv[1], hv[2], hv[3]);
            *(uint4*)(DST_L + base + j8*8) = make_uint4(lv[0], lv[1], lv[2], lv[3]);
        }
    } else {
        int d_idx = tid >> 5;
        int s4    = (tid & 31) * 4;
        int sg    = (by & 15)*128 + s4;
#pragma unroll
        for (int dd = 0; dd < 16; dd++) {
            int d = dd*8 + d_idx;
            int n = bxx*128 + d;
            int hh = n >> 6, dg = n & 63;
            uint32_t h0, l0, h1, l1;
            bsplit(h0, l0, Cs[s4][d],   Cs[s4+1][d]);
            bsplit(h1, l1, Cs[s4+2][d], Cs[s4+3][d]);
            size_t base = ((size_t)(b*NH + hh)*DH + dg)*SEQ + sg;
            *(uint2*)(g_vh + base) = make_uint2(h0, h1);
            *(uint2*)(g_vl + base) = make_uint2(l0, l1);
        }
    }
#undef ISSUE
}

// ---------------- flash attention, HMMA bf16 3-pass, 3-stage 1-barrier ------
#define AT_STG 32768
#define AT_SMEM (3*AT_STG)      // 98304
__global__ __launch_bounds__(128, 2) void attn_mma() {
    extern __shared__ __align__(16) char asmem[];
    uint32_t sb = smem_u32(asmem);
    const int tid = threadIdx.x, lane = tid & 31, w = tid >> 5;
    const int bh = blockIdx.y, h = bh & (NH-1), b = bh >> 4;
    const int q0 = blockIdx.x * 64;
    const int lr8 = lane & 7, lg = lane >> 3;
    const int r0 = w*16 + (lane >> 2);
    const int qc = 2*(lane & 3);

    const __nv_bfloat16* Qh_g = g_qh + ((size_t)bh*SEQ + q0)*DH;
    const __nv_bfloat16* Ql_g = g_ql + ((size_t)bh*SEQ + q0)*DH;
    const __nv_bfloat16* Kh_g = g_kh + (size_t)bh*SEQ*DH;
    const __nv_bfloat16* Kl_g = g_kl + (size_t)bh*SEQ*DH;
    const __nv_bfloat16* Vh_g = g_vh + (size_t)bh*DH*SEQ;
    const __nv_bfloat16* Vl_g = g_vl + (size_t)bh*DH*SEQ;
    const float* biasrow = g_bias + h*4096;

    uint32_t aqh[4][4], aql[4][4];
#pragma unroll
    for (int kt = 0; kt < 4; kt++) {
        int c0 = kt*16 + qc;
        aqh[kt][0] = *(const uint32_t*)(Qh_g + (size_t)r0*DH + c0);
        aqh[kt][1] = *(const uint32_t*)(Qh_g + (size_t)(r0+8)*DH + c0);
        aqh[kt][2] = *(const uint32_t*)(Qh_g + (size_t)r0*DH + c0 + 8);
        aqh[kt][3] = *(const uint32_t*)(Qh_g + (size_t)(r0+8)*DH + c0 + 8);
        aql[kt][0] = *(const uint32_t*)(Ql_g + (size_t)r0*DH + c0);
        aql[kt][1] = *(const uint32_t*)(Ql_g + (size_t)(r0+8)*DH + c0);
        aql[kt][2] = *(const uint32_t*)(Ql_g + (size_t)r0*DH + c0 + 8);
        aql[kt][3] = *(const uint32_t*)(Ql_g + (size_t)(r0+8)*DH + c0 + 8);
    }

    float o[8][4];
#pragma unroll
    for (int nt = 0; nt < 8; nt++)
#pragma unroll
        for (int e = 0; e < 4; e++) o[nt][e] = 0.f;
    float m0 = -1e30f, m1 = -1e30f, l0 = 0.f, l1 = 0.f;

#define AISSUE(it_) do {                                                        \
    int k0_ = (it_)*64;                                                         \
    uint32_t stb_ = sb + ((it_) % 3)*AT_STG;                                    \
    _Pragma("unroll")                                                           \
    for (int i_ = 0; i_ < 16; i_++) {                                           \
        int id_ = tid + i_*128;                                                 \
        int arr_ = id_ >> 9, rem_ = id_ & 511, row_ = rem_ >> 3, bk_ = rem_ & 7;\
        uint32_t dst_ = stb_ + arr_*8192 + row_*128 + ((bk_ ^ (row_ & 7))*16);  \
        const __nv_bfloat16* src_;                                              \
        if (arr_ == 0)      src_ = Kh_g + (size_t)(k0_ + row_)*DH + bk_*8;      \
        else if (arr_ == 1) src_ = Kl_g + (size_t)(k0_ + row_)*DH + bk_*8;      \
        else if (arr_ == 2) src_ = Vh_g + (size_t)row_*SEQ + k0_ + bk_*8;       \
        else                src_ = Vl_g + (size_t)row_*SEQ + k0_ + bk_*8;       \
        cpa16(dst_, src_);                                                      \
    }                                                                           \
    asm volatile("cp.async.commit_group;" ::: "memory");                        \
} while (0)

    AISSUE(0);
    AISSUE(1);

    for (int it = 0; it < 32; it++) {
        if (it < 31) asm volatile("cp.async.wait_group 1;" ::: "memory");
        else         asm volatile("cp.async.wait_group 0;" ::: "memory");
        __syncthreads();                 // single barrier per iteration
        if (it < 30) AISSUE(it + 2);     // writes stage (it-1)%3, safe after barrier
        uint32_t stg = sb + (it % 3)*AT_STG;

        // ---- S = Q K^T (3-pass, pass-outer over nb within each kt)
        float sc[8][4];
#pragma unroll
        for (int nt = 0; nt < 8; nt++)
#pragma unroll
            for (int e = 0; e < 4; e++) sc[nt][e] = 0.f;

#pragma unroll
        for (int kt = 0; kt < 4; kt++) {
            uint32_t kh[4][4], kl[4][4];
#pragma unroll
            for (int nb = 0; nb < 4; nb++) {
                int row = nb*16 + lr8 + (lg >> 1)*8;
                int bk  = 2*kt + (lg & 1);
                uint32_t ad = stg + row*128 + ((bk ^ (row & 7))*16);
                ldsm4(kh[nb], ad);
                ldsm4(kl[nb], ad + 8192);
            }
#pragma unroll
            for (int nb = 0; nb < 4; nb++) {
                mma16816(sc[2*nb],   aqh[kt], kh[nb][0], kh[nb][1]);
                mma16816(sc[2*nb+1], aqh[kt], kh[nb][2], kh[nb][3]);
            }
#pragma unroll
            for (int nb = 0; nb < 4; nb++) {
                mma16816(sc[2*nb],   aqh[kt], kl[nb][0], kl[nb][1]);
                mma16816(sc[2*nb+1], aqh[kt], kl[nb][2], kl[nb][3]);
            }
#pragma unroll
            for (int nb = 0; nb < 4; nb++) {
                mma16816(sc[2*nb],   aql[kt], kh[nb][0], kh[nb][1]);
                mma16816(sc[2*nb+1], aql[kt], kh[nb][2], kh[nb][3]);
            }
        }

        {
            int relb = it*64 + qc - (q0 + r0) + 2047;
            float bb0[9], bb1[9];
#pragma unroll
            for (int t = 0; t < 9; t++) {
                bb0[t] = biasrow[relb - 8 + t*8];
                bb1[t] = biasrow[relb - 7 + t*8];
            }
#pragma unroll
            for (int nt = 0; nt < 8; nt++) {
                sc[nt][0] += bb0[nt+1]; sc[nt][1] += bb1[nt+1];
                sc[nt][2] += bb0[nt];   sc[nt][3] += bb1[nt];
            }
        }

        float mx0 = sc[0][0], mx1 = sc[0][2];
#pragma unroll
        for (int nt = 0; nt < 8; nt++) {
            mx0 = fmaxf(mx0, fmaxf(sc[nt][0], sc[nt][1]));
            mx1 = fmaxf(mx1, fmaxf(sc[nt][2], sc[nt][3]));
        }
        mx0 = fmaxf(mx0, __shfl_xor_sync(0xffffffffu, mx0, 1));
        mx0 = fmaxf(mx0, __shfl_xor_sync(0xffffffffu, mx0, 2));
        mx1 = fmaxf(mx1, __shfl_xor_sync(0xffffffffu, mx1, 1));
        mx1 = fmaxf(mx1, __shfl_xor_sync(0xffffffffu, mx1, 2));
        float m0n = fmaxf(m0, mx0), m1n = fmaxf(m1, mx1);
        float c0 = __expf(m0 - m0n), c1 = __expf(m1 - m1n);
        m0 = m0n; m1 = m1n;
        float s0 = 0.f, s1 = 0.f;
#pragma unroll
        for (int nt = 0; nt < 8; nt++) {
            sc[nt][0] = __expf(sc[nt][0] - m0n);
            sc[nt][1] = __expf(sc[nt][1] - m0n);
            sc[nt][2] = __expf(sc[nt][2] - m1n);
            sc[nt][3] = __expf(sc[nt][3] - m1n);
            s0 += sc[nt][0] + sc[nt][1];
            s1 += sc[nt][2] + sc[nt][3];
        }
        s0 += __shfl_xor_sync(0xffffffffu, s0, 1);
        s0 += __shfl_xor_sync(0xffffffffu, s0, 2);
        s1 += __shfl_xor_sync(0xffffffffu, s1, 1);
        s1 += __shfl_xor_sync(0xffffffffu, s1, 2);
        l0 = l0*c0 + s0; l1 = l1*c1 + s1;
#pragma unroll
        for (int nt = 0; nt < 8; nt++) {
            o[nt][0] *= c0; o[nt][1] *= c0;
            o[nt][2] *= c1; o[nt][3] *= c1;
        }

        // ---- O += P V (3-pass, pass-outer over nb within each kt)
#pragma unroll
        for (int kt = 0; kt < 4; kt++) {
            uint32_t ph[4], pl[4];
            bsplit(ph[0], pl[0], sc[2*kt][0],   sc[2*kt][1]);
            bsplit(ph[1], pl[1], sc[2*kt][2],   sc[2*kt][3]);
            bsplit(ph[2], pl[2], sc[2*kt+1][0], sc[2*kt+1][1]);
            bsplit(ph[3], pl[3], sc[2*kt+1][2], sc[2*kt+1][3]);
            uint32_t vh[4][4], vl[4][4];
#pragma unroll
            for (int nb = 0; nb < 4; nb++) {
                int row = nb*16 + lr8 + (lg >> 1)*8;
                int bk  = 2*kt + (lg & 1);
                uint32_t ad = stg + 16384 + row*128 + ((bk ^ (row & 7))*16);
                ldsm4(vh[nb], ad);
                ldsm4(vl[nb], ad + 8192);
            }
#pragma unroll
            for (int nb = 0; nb < 4; nb++) {
                mma16816(o[2*nb],   ph, vh[nb][0], vh[nb][1]);
                mma16816(o[2*nb+1], ph, vh[nb][2], vh[nb][3]);
            }
#pragma unroll
            for (int nb = 0; nb < 4; nb++) {
                mma16816(o[2*nb],   ph, vl[nb][0], vl[nb][1]);
                mma16816(o[2*nb+1], ph, vl[nb][2], vl[nb][3]);
            }
#pragma unroll
            for (int nb = 0; nb < 4; nb++) {
                mma16816(o[2*nb],   pl, vh[nb][0], vh[nb][1]);
                mma16816(o[2*nb+1], pl, vh[nb][2], vh[nb][3]);
            }
        }
    }

    float inv0 = 1.0f / l0, inv1 = 1.0f / l1;
    size_t ro0 = ((size_t)b*SEQ + q0 + r0)*DM + h*DH + qc;
    size_t ro1 = ro0 + (size_t)8*DM;
#pragma unroll
    for (int nt = 0; nt < 8; nt++) {
        uint32_t hv, lv;
        bsplit(hv, lv, o[nt][0]*inv0, o[nt][1]*inv0);
        *(uint32_t*)(g_oh + ro0 + nt*8) = hv;
        *(uint32_t*)(g_ol + ro0 + nt*8) = lv;
        bsplit(hv, lv, o[nt][2]*inv1, o[nt][3]*inv1);
        *(uint32_t*)(g_oh + ro1 + nt*8) = hv;
        *(uint32_t*)(g_ol + ro1 + nt*8) = lv;
    }
#undef AISSUE
}

// ---------------- launch -----------------------------------------------------
extern "C" void kernel_launch(void* const* d_in, const int* in_sizes, int n_in,
                              void* d_out, int out_size) {
    const float* X   = (const float*)d_in[0];
    const float* Wq  = (const float*)d_in[1];
    const float* Wk  = (const float*)d_in[2];
    const float* Wv  = (const float*)d_in[3];
    const float* Wo  = (const float*)d_in[4];
    const float* rel = (const float*)d_in[5];
    float* out = (float*)d_out;

    cudaFuncSetAttribute(gemm_mma, cudaFuncAttributeMaxDynamicSharedMemorySize, G_SMEM);
    cudaFuncSetAttribute(attn_mma, cudaFuncAttributeMaxDynamicSharedMemorySize, AT_SMEM);

    bias_kernel<<<16, 256>>>(rel);
    conv_split<<<4096, 256>>>((const float4*)X);
    conv_wT<<<dim3(32, 32, 4), dim3(32, 8)>>>(Wq, Wk, Wv, Wo);

    gemm_mma<<<dim3(24, 32), 256, G_SMEM>>>(1, nullptr);   // fused QKV

    attn_mma<<<dim3(SEQ/64, BATCH*NH), 128, AT_SMEM>>>();

    gemm_mma<<<dim3(8, 32), 256, G_SMEM>>>(0, out);        // O projection
}

// round 14
// speedup vs baseline: 1.4648x; 1.4648x over previous
#include <cuda_runtime.h>
#include <cuda_bf16.h>
#include <math.h>
#include <stdint.h>

#define NH   16
#define DH   64
#define SEQ  2048
#define BATCH 2
#define DM   1024
#define MROWS (BATCH*SEQ)   // 4096

__device__ __forceinline__ uint32_t smem_u32(const void* p) {
    uint32_t a;
    asm("{ .reg .u64 t; cvta.to.shared.u64 t, %1; cvt.u32.u64 %0, t; }"
        : "=r"(a) : "l"(p));
    return a;
}
__device__ __forceinline__ void cpa16(uint32_t s, const void* g) {
    asm volatile("cp.async.cg.shared.global [%0], [%1], 16;" :: "r"(s), "l"(g));
}
__device__ __forceinline__ void ldsm4(uint32_t r[4], uint32_t a) {
    asm volatile("ldmatrix.sync.aligned.m8n8.x4.shared.b16 {%0,%1,%2,%3}, [%4];"
                 : "=r"(r[0]), "=r"(r[1]), "=r"(r[2]), "=r"(r[3]) : "r"(a));
}
__device__ __forceinline__ void mma16816(float c[4], const uint32_t a[4],
                                         const uint32_t b0, const uint32_t b1) {
    asm volatile("mma.sync.aligned.m16n8k16.row.col.f32.bf16.bf16.f32 "
        "{%0,%1,%2,%3}, {%4,%5,%6,%7}, {%8,%9}, {%0,%1,%2,%3};"
        : "+f"(c[0]), "+f"(c[1]), "+f"(c[2]), "+f"(c[3])
        : "r"(a[0]), "r"(a[1]), "r"(a[2]), "r"(a[3]), "r"(b0), "r"(b1));
}
__device__ __forceinline__ uint32_t cvt2(float x, float y) {
    uint32_t r; asm("cvt.rn.bf16x2.f32 %0, %1, %2;" : "=r"(r) : "f"(y), "f"(x));
    return r;
}
__device__ __forceinline__ void bsplit(uint32_t &hi, uint32_t &lo, float x, float y) {
    uint32_t h = cvt2(x, y);
    float xr = x - __uint_as_float(h << 16);
    float yr = y - __uint_as_float(h & 0xffff0000u);
    hi = h; lo = cvt2(xr, yr);
}

// ---------------- scratch (device globals; no allocations allowed) ----------
__device__ float g_bias[NH*4096];                      // [h][rel+2047]
__device__ __nv_bfloat16 g_xh[(size_t)MROWS*DM];       // X hi
__device__ __nv_bfloat16 g_xl[(size_t)MROWS*DM];       // X lo
__device__ __nv_bfloat16 g_oh[(size_t)MROWS*DM];       // attn-out hi
__device__ __nv_bfloat16 g_ol[(size_t)MROWS*DM];       // attn-out lo
__device__ __nv_bfloat16 g_wth[4*(size_t)DM*DM];       // W^T hi [w][n][k]
__device__ __nv_bfloat16 g_wtl[4*(size_t)DM*DM];       // W^T lo
__device__ __nv_bfloat16 g_qh[(size_t)BATCH*NH*SEQ*DH];  // Q hi [b,h,s,d]
__device__ __nv_bfloat16 g_ql[(size_t)BATCH*NH*SEQ*DH];
__device__ __nv_bfloat16 g_kh[(size_t)BATCH*NH*SEQ*DH];  // K hi [b,h,s,d]
__device__ __nv_bfloat16 g_kl[(size_t)BATCH*NH*SEQ*DH];
__device__ __nv_bfloat16 g_vh[(size_t)BATCH*NH*DH*SEQ];  // V hi [b,h,d,s]
__device__ __nv_bfloat16 g_vl[(size_t)BATCH*NH*DH*SEQ];

// ---------------- relative-position bias table ------------------------------
__global__ void bias_kernel(const float* __restrict__ rel_emb) {
    int idx = blockIdx.x * blockDim.x + threadIdx.x;   // 0..4094
    if (idx >= 4095) return;
    int rel = idx - 2047;
    int bucket = (rel > 0) ? 16 : 0;
    int r = abs(rel);
    int bval;
    if (r < 8) bval = r;
    else {
        float v = logf((float)r / 8.0f) / 2.772588722239781f * 8.0f;
        bval = min(8 + (int)v, 15);
    }
    bucket += bval;
#pragma unroll
    for (int h = 0; h < NH; h++)
        g_bias[h*4096 + idx] = rel_emb[bucket*NH + h];
}

// ---------------- fp32 -> bf16 hi/lo split of X -----------------------------
__global__ void conv_split(const float4* __restrict__ src) {
    int i = blockIdx.x * blockDim.x + threadIdx.x;    // 1048576
    float4 v = src[i];
    uint32_t h0, l0, h1, l1;
    bsplit(h0, l0, v.x, v.y);
    bsplit(h1, l1, v.z, v.w);
    ((uint32_t*)g_xh)[2*i] = h0; ((uint32_t*)g_xh)[2*i+1] = h1;
    ((uint32_t*)g_xl)[2*i] = l0; ((uint32_t*)g_xl)[2*i+1] = l1;
}

// ---------------- weight transpose + split: W[K][N] -> W^T[N][K] bf16 -------
__global__ void conv_wT(const float* __restrict__ W0, const float* __restrict__ W1,
                        const float* __restrict__ W2, const float* __restrict__ W3) {
    __shared__ float t[32][33];
    int z = blockIdx.z;
    const float* W = (z == 0) ? W0 : (z == 1) ? W1 : (z == 2) ? W2 : W3;
    __nv_bfloat16* oh = g_wth + (size_t)z*DM*DM;
    __nv_bfloat16* ol = g_wtl + (size_t)z*DM*DM;
    int k0 = blockIdx.y*32, n0 = blockIdx.x*32;
    int tx = threadIdx.x, ty = threadIdx.y;   // (32, 8)
#pragma unroll
    for (int j = 0; j < 4; j++)
        t[tx][ty + 8*j] = W[(size_t)(k0 + ty + 8*j)*DM + n0 + tx];
    __syncthreads();
#pragma unroll
    for (int j = 0; j < 4; j++) {
        float v = t[ty + 8*j][tx];
        __nv_bfloat16 h = __float2bfloat16(v);
        __nv_bfloat16 l = __float2bfloat16(v - __bfloat162float(h));
        size_t o = (size_t)(n0 + ty + 8*j)*DM + k0 + tx;
        oh[o] = h; ol[o] = l;
    }
}

// ---------------- warp-MMA GEMM (HMMA bf16, 3-pass hi/lo) -------------------
// CTA tile 128x128, 8 warps of 64x32, K chunk 32.
// 3-stage single-barrier cp.async pipeline; pad-free XOR-swizzled 64B rows.
#define AST    32768            // stage: 4 arrays x 128 rows x 64B
#define OFF_AH 0
#define OFF_AL 8192
#define OFF_BH 16384
#define OFF_BL 24576
#define G_SMEM (3*AST)          // 98304

__global__ __launch_bounds__(256) void gemm_mma(int fused, float* __restrict__ Cext) {
    extern __shared__ __align__(16) char sm[];
    uint32_t sb = smem_u32(sm);
    const int tid = threadIdx.x, lane = tid & 31, w = tid >> 5;
    const int wm = w >> 2, wn = w & 3;
    const int by = blockIdx.y;

    int wsel, bxx, cmode;
    if (fused) { wsel = blockIdx.x >> 3; bxx = blockIdx.x & 7; cmode = wsel; }
    else       { wsel = 3; bxx = blockIdx.x; cmode = 3; }

    const __nv_bfloat16* Ah = (fused ? g_xh : g_oh) + (size_t)(by*128)*DM;
    const __nv_bfloat16* Al = (fused ? g_xl : g_ol) + (size_t)(by*128)*DM;
    const __nv_bfloat16* Bh = g_wth + (size_t)wsel*DM*DM + (size_t)(bxx*128)*DM;
    const __nv_bfloat16* Bl = g_wtl + (size_t)wsel*DM*DM + (size_t)(bxx*128)*DM;

    const int lr  = tid >> 2;
    const int blk = tid & 3;

    float acc[4][4][4];
#pragma unroll
    for (int mt = 0; mt < 4; mt++)
#pragma unroll
        for (int nt = 0; nt < 4; nt++)
#pragma unroll
            for (int e = 0; e < 4; e++) acc[mt][nt][e] = 0.f;

    uint32_t aRow[4], aXr[4], bRow[2], bXr[2];
#pragma unroll
    for (int mt = 0; mt < 4; mt++) {
        int row = wm*64 + mt*16 + (lane & 15);
        aRow[mt] = (uint32_t)row * 64;
        aXr[mt]  = (uint32_t)((row >> 1) & 3);
    }
    {
        int br0 = wn*32 + (lane & 7) + ((lane >> 4) & 1) * 8;
        int br1 = br0 + 16;
        bRow[0] = (uint32_t)br0 * 64; bXr[0] = (uint32_t)((br0 >> 1) & 3);
        bRow[1] = (uint32_t)br1 * 64; bXr[1] = (uint32_t)((br1 >> 1) & 3);
    }
    const uint32_t cbiA = (uint32_t)(lane >> 4);
    const uint32_t cbiB = (uint32_t)((lane >> 3) & 1);

#define ISSUE(c) do {                                                          \
    uint32_t stb_ = sb + ((c) % 3) * AST;                                      \
    int kofs_ = (c)*32 + blk*8;                                                \
    _Pragma("unroll")                                                          \
    for (int half = 0; half < 2; half++) {                                     \
        int r_ = lr + half*64;                                                 \
        uint32_t so_ = (uint32_t)r_*64 + (((uint32_t)blk ^ ((r_>>1)&3))*16);   \
        size_t go_ = (size_t)r_*DM + kofs_;                                    \
        cpa16(stb_ + OFF_AH + so_, Ah + go_);                                  \
        cpa16(stb_ + OFF_AL + so_, Al + go_);                                  \
        cpa16(stb_ + OFF_BH + so_, Bh + go_);                                  \
        cpa16(stb_ + OFF_BL + so_, Bl + go_);                                  \
    }                                                                          \
    asm volatile("cp.async.commit_group;" ::: "memory");                       \
} while (0)

    ISSUE(0);
    ISSUE(1);

    for (int c = 0; c < 32; c++) {
        if (c < 31) asm volatile("cp.async.wait_group 1;" ::: "memory");
        else        asm volatile("cp.async.wait_group 0;" ::: "memory");
        __syncthreads();
        if (c < 30) ISSUE(c + 2);

        uint32_t stb = sb + (c % 3) * AST;
#pragma unroll
        for (int s = 0; s < 2; s++) {
            uint32_t ah[4][4], al[4][4], bh[2][4], bl[2][4];
            uint32_t bA = 2*s + cbiA;
            uint32_t bB = 2*s + cbiB;
#pragma unroll
            for (int mt = 0; mt < 4; mt++) {
                uint32_t off = aRow[mt] + ((bA ^ aXr[mt]) << 4);
                ldsm4(ah[mt], stb + OFF_AH + off);
                ldsm4(al[mt], stb + OFF_AL + off);
            }
#pragma unroll
            for (int p = 0; p < 2; p++) {
                uint32_t off = bRow[p] + ((bB ^ bXr[p]) << 4);
                ldsm4(bh[p], stb + OFF_BH + off);
                ldsm4(bl[p], stb + OFF_BL + off);
            }
#pragma unroll
            for (int mt = 0; mt < 4; mt++)
#pragma unroll
                for (int nt = 0; nt < 4; nt++) {
                    const uint32_t* bth = bh[nt >> 1] + (nt & 1) * 2;
                    mma16816(acc[mt][nt], ah[mt], bth[0], bth[1]);
                }
#pragma unroll
            for (int mt = 0; mt < 4; mt++)
#pragma unroll
                for (int nt = 0; nt < 4; nt++) {
                    const uint32_t* btl = bl[nt >> 1] + (nt & 1) * 2;
                    mma16816(acc[mt][nt], ah[mt], btl[0], btl[1]);
                }
#pragma unroll
            for (int mt = 0; mt < 4; mt++)
#pragma unroll
                for (int nt = 0; nt < 4; nt++) {
                    const uint32_t* bth = bh[nt >> 1] + (nt & 1) * 2;
                    mma16816(acc[mt][nt], al[mt], bth[0], bth[1]);
                }
        }
    }
    __syncthreads();

    float (*Cs)[136] = (float (*)[136])sm;
#pragma unroll
    for (int mt = 0; mt < 4; mt++)
#pragma unroll
        for (int nt = 0; nt < 4; nt++) {
            int row = wm*64 + mt*16 + (lane >> 2);
            int col = wn*32 + nt*8 + 2*(lane & 3);
            Cs[row    ][col] = acc[mt][nt][0]; Cs[row    ][col+1] = acc[mt][nt][1];
            Cs[row + 8][col] = acc[mt][nt][2]; Cs[row + 8][col+1] = acc[mt][nt][3];
        }
    __syncthreads();

    int b = by >> 4;
    if (cmode == 3) {
        int mr = tid >> 1, half = tid & 1;
        const float* src = &Cs[mr][half*64];
        float* dst = Cext + (size_t)(by*128 + mr)*DM + bxx*128 + half*64;
#pragma unroll
        for (int j = 0; j < 16; j++)
            ((float4*)dst)[j] = ((const float4*)src)[j];
    } else if (cmode <= 1) {
        int mr = tid >> 1, half = tid & 1;
        int hh = bxx*2 + half;
        int s  = (by & 15)*128 + mr;
        __nv_bfloat16* DST_H = cmode ? g_kh : g_qh;
        __nv_bfloat16* DST_L = cmode ? g_kl : g_ql;
        size_t base = ((size_t)(b*NH + hh)*SEQ + s)*DH;
        const float* src = &Cs[mr][half*64];
#pragma unroll
        for (int j8 = 0; j8 < 8; j8++) {
            uint32_t hv[4], lv[4];
#pragma unroll
            for (int e = 0; e < 4; e++)
                bsplit(hv[e], lv[e], src[j8*8 + 2*e], src[j8*8 + 2*e + 1]);
            *(uint4*)(DST_H + base + j8*8) = make_uint4(hv[0], hv[1], hv[2], hv[3]);
            *(uint4*)(DST_L + base + j8*8) = make_uint4(lv[0], lv[1], lv[2], lv[3]);
        }
    } else {
        int d_idx = tid >> 5;
        int s4    = (tid & 31) * 4;
        int sg    = (by & 15)*128 + s4;
#pragma unroll
        for (int dd = 0; dd < 16; dd++) {
            int d = dd*8 + d_idx;
            int n = bxx*128 + d;
            int hh = n >> 6, dg = n & 63;
            uint32_t h0, l0, h1, l1;
            bsplit(h0, l0, Cs[s4][d],   Cs[s4+1][d]);
            bsplit(h1, l1, Cs[s4+2][d], Cs[s4+3][d]);
            size_t base = ((size_t)(b*NH + hh)*DH + dg)*SEQ + sg;
            *(uint2*)(g_vh + base) = make_uint2(h0, h1);
            *(uint2*)(g_vl + base) = make_uint2(l0, l1);
        }
    }
#undef ISSUE
}

// ---------------- flash attention, HMMA bf16 3-pass -------------------------
// 128 queries / CTA, 8 warps (256 thr), 2-stage K/V pipeline (R11 structure).
#define AT_STG 32768
__global__ __launch_bounds__(256, 2) void attn_mma() {
    extern __shared__ __align__(16) char asmem[];
    uint32_t sb = smem_u32(asmem);
    const int tid = threadIdx.x, lane = tid & 31, w = tid >> 5;
    const int bh = blockIdx.y, h = bh & (NH-1), b = bh >> 4;
    const int q0 = blockIdx.x * 128;
    const int lr8 = lane & 7, lg = lane >> 3;
    const int r0 = w*16 + (lane >> 2);          // 0..127
    const int qc = 2*(lane & 3);

    const __nv_bfloat16* Qh_g = g_qh + ((size_t)bh*SEQ + q0)*DH;
    const __nv_bfloat16* Ql_g = g_ql + ((size_t)bh*SEQ + q0)*DH;
    const __nv_bfloat16* Kh_g = g_kh + (size_t)bh*SEQ*DH;
    const __nv_bfloat16* Kl_g = g_kl + (size_t)bh*SEQ*DH;
    const __nv_bfloat16* Vh_g = g_vh + (size_t)bh*DH*SEQ;
    const __nv_bfloat16* Vl_g = g_vl + (size_t)bh*DH*SEQ;
    const float* biasrow = g_bias + h*4096;

    uint32_t aqh[4][4], aql[4][4];
#pragma unroll
    for (int kt = 0; kt < 4; kt++) {
        int c0 = kt*16 + qc;
        aqh[kt][0] = *(const uint32_t*)(Qh_g + (size_t)r0*DH + c0);
        aqh[kt][1] = *(const uint32_t*)(Qh_g + (size_t)(r0+8)*DH + c0);
        aqh[kt][2] = *(const uint32_t*)(Qh_g + (size_t)r0*DH + c0 + 8);
        aqh[kt][3] = *(const uint32_t*)(Qh_g + (size_t)(r0+8)*DH + c0 + 8);
        aql[kt][0] = *(const uint32_t*)(Ql_g + (size_t)r0*DH + c0);
        aql[kt][1] = *(const uint32_t*)(Ql_g + (size_t)(r0+8)*DH + c0);
        aql[kt][2] = *(const uint32_t*)(Ql_g + (size_t)r0*DH + c0 + 8);
        aql[kt][3] = *(const uint32_t*)(Ql_g + (size_t)(r0+8)*DH + c0 + 8);
    }

    float o[8][4];
#pragma unroll
    for (int nt = 0; nt < 8; nt++)
#pragma unroll
        for (int e = 0; e < 4; e++) o[nt][e] = 0.f;
    float m0 = -1e30f, m1 = -1e30f, l0 = 0.f, l1 = 0.f;

#define AISSUE(it_) do {                                                        \
    int k0_ = (it_)*64;                                                         \
    uint32_t stb_ = sb + ((it_) & 1)*AT_STG;                                    \
    _Pragma("unroll")                                                           \
    for (int i_ = 0; i_ < 8; i_++) {                                            \
        int id_ = tid + i_*256;                                                 \
        int arr_ = id_ >> 9, rem_ = id_ & 511, row_ = rem_ >> 3, bk_ = rem_ & 7;\
        uint32_t dst_ = stb_ + arr_*8192 + row_*128 + ((bk_ ^ (row_ & 7))*16);  \
        const __nv_bfloat16* src_;                                              \
        if (arr_ == 0)      src_ = Kh_g + (size_t)(k0_ + row_)*DH + bk_*8;      \
        else if (arr_ == 1) src_ = Kl_g + (size_t)(k0_ + row_)*DH + bk_*8;      \
        else if (arr_ == 2) src_ = Vh_g + (size_t)row_*SEQ + k0_ + bk_*8;       \
        else                src_ = Vl_g + (size_t)row_*SEQ + k0_ + bk_*8;       \
        cpa16(dst_, src_);                                                      \
    }                                                                           \
    asm volatile("cp.async.commit_group;" ::: "memory");                        \
} while (0)

    AISSUE(0);
    AISSUE(1);

    for (int it = 0; it < 32; it++) {
        if (it < 31) asm volatile("cp.async.wait_group 1;" ::: "memory");
        else         asm volatile("cp.async.wait_group 0;" ::: "memory");
        __syncthreads();
        uint32_t stg = sb + (it & 1)*AT_STG;

        // ---- S = Q K^T (3-pass, pass-outer over nb within each kt)
        float sc[8][4];
#pragma unroll
        for (int nt = 0; nt < 8; nt++)
#pragma unroll
            for (int e = 0; e < 4; e++) sc[nt][e] = 0.f;

#pragma unroll
        for (int kt = 0; kt < 4; kt++) {
            uint32_t kh[4][4], kl[4][4];
#pragma unroll
            for (int nb = 0; nb < 4; nb++) {
                int row = nb*16 + lr8 + (lg >> 1)*8;
                int bk  = 2*kt + (lg & 1);
                uint32_t ad = stg + row*128 + ((bk ^ (row & 7))*16);
                ldsm4(kh[nb], ad);
                ldsm4(kl[nb], ad + 8192);
            }
#pragma unroll
            for (int nb = 0; nb < 4; nb++) {
                mma16816(sc[2*nb],   aqh[kt], kh[nb][0], kh[nb][1]);
                mma16816(sc[2*nb+1], aqh[kt], kh[nb][2], kh[nb][3]);
            }
#pragma unroll
            for (int nb = 0; nb < 4; nb++) {
                mma16816(sc[2*nb],   aqh[kt], kl[nb][0], kl[nb][1]);
                mma16816(sc[2*nb+1], aqh[kt], kl[nb][2], kl[nb][3]);
            }
#pragma unroll
            for (int nb = 0; nb < 4; nb++) {
                mma16816(sc[2*nb],   aql[kt], kh[nb][0], kh[nb][1]);
                mma16816(sc[2*nb+1], aql[kt], kh[nb][2], kh[nb][3]);
            }
        }

        {
            int relb = it*64 + qc - (q0 + r0) + 2047;
            float bb0[9], bb1[9];
#pragma unroll
            for (int t = 0; t < 9; t++) {
                bb0[t] = biasrow[relb - 8 + t*8];
                bb1[t] = biasrow[relb - 7 + t*8];
            }
#pragma unroll
            for (int nt = 0; nt < 8; nt++) {
                sc[nt][0] += bb0[nt+1]; sc[nt][1] += bb1[nt+1];
                sc[nt][2] += bb0[nt];   sc[nt][3] += bb1[nt];
            }
        }

        float mx0 = sc[0][0], mx1 = sc[0][2];
#pragma unroll
        for (int nt = 0; nt < 8; nt++) {
            mx0 = fmaxf(mx0, fmaxf(sc[nt][0], sc[nt][1]));
            mx1 = fmaxf(mx1, fmaxf(sc[nt][2], sc[nt][3]));
        }
        mx0 = fmaxf(mx0, __shfl_xor_sync(0xffffffffu, mx0, 1));
        mx0 = fmaxf(mx0, __shfl_xor_sync(0xffffffffu, mx0, 2));
        mx1 = fmaxf(mx1, __shfl_xor_sync(0xffffffffu, mx1, 1));
        mx1 = fmaxf(mx1, __shfl_xor_sync(0xffffffffu, mx1, 2));
        float m0n = fmaxf(m0, mx0), m1n = fmaxf(m1, mx1);
        float c0 = __expf(m0 - m0n), c1 = __expf(m1 - m1n);
        m0 = m0n; m1 = m1n;
        float s0 = 0.f, s1 = 0.f;
#pragma unroll
        for (int nt = 0; nt < 8; nt++) {
            sc[nt][0] = __expf(sc[nt][0] - m0n);
            sc[nt][1] = __expf(sc[nt][1] - m0n);
            sc[nt][2] = __expf(sc[nt][2] - m1n);
            sc[nt][3] = __expf(sc[nt][3] - m1n);
            s0 += sc[nt][0] + sc[nt][1];
            s1 += sc[nt][2] + sc[nt][3];
        }
        s0 += __shfl_xor_sync(0xffffffffu, s0, 1);
        s0 += __shfl_xor_sync(0xffffffffu, s0, 2);
        s1 += __shfl_xor_sync(0xffffffffu, s1, 1);
        s1 += __shfl_xor_sync(0xffffffffu, s1, 2);
        l0 = l0*c0 + s0; l1 = l1*c1 + s1;
#pragma unroll
        for (int nt = 0; nt < 8; nt++) {
            o[nt][0] *= c0; o[nt][1] *= c0;
            o[nt][2] *= c1; o[nt][3] *= c1;
        }

        // ---- O += P V (3-pass, pass-outer over nb within each kt)
#pragma unroll
        for (int kt = 0; kt < 4; kt++) {
            uint32_t ph[4], pl[4];
            bsplit(ph[0], pl[0], sc[2*kt][0],   sc[2*kt][1]);
            bsplit(ph[1], pl[1], sc[2*kt][2],   sc[2*kt][3]);
            bsplit(ph[2], pl[2], sc[2*kt+1][0], sc[2*kt+1][1]);
            bsplit(ph[3], pl[3], sc[2*kt+1][2], sc[2*kt+1][3]);
            uint32_t vh[4][4], vl[4][4];
#pragma unroll
            for (int nb = 0; nb < 4; nb++) {
                int row = nb*16 + lr8 + (lg >> 1)*8;
                int bk  = 2*kt + (lg & 1);
                uint32_t ad = stg + 16384 + row*128 + ((bk ^ (row & 7))*16);
                ldsm4(vh[nb], ad);
                ldsm4(vl[nb], ad + 8192);
            }
#pragma unroll
            for (int nb = 0; nb < 4; nb++) {
                mma16816(o[2*nb],   ph, vh[nb][0], vh[nb][1]);
                mma16816(o[2*nb+1], ph, vh[nb][2], vh[nb][3]);
            }
#pragma unroll
            for (int nb = 0; nb < 4; nb++) {
                mma16816(o[2*nb],   ph, vl[nb][0], vl[nb][1]);
                mma16816(o[2*nb+1], ph, vl[nb][2], vl[nb][3]);
            }
#pragma unroll
            for (int nb = 0; nb < 4; nb++) {
                mma16816(o[2*nb],   pl, vh[nb][0], vh[nb][1]);
                mma16816(o[2*nb+1], pl, vh[nb][2], vh[nb][3]);
            }
        }
        __syncthreads();
        if (it + 2 < 32) AISSUE(it + 2);
    }

    float inv0 = 1.0f / l0, inv1 = 1.0f / l1;
    size_t ro0 = ((size_t)b*SEQ + q0 + r0)*DM + h*DH + qc;
    size_t ro1 = ro0 + (size_t)8*DM;
#pragma unroll
    for (int nt = 0; nt < 8; nt++) {
        uint32_t hv, lv;
        bsplit(hv, lv, o[nt][0]*inv0, o[nt][1]*inv0);
        *(uint32_t*)(g_oh + ro0 + nt*8) = hv;
        *(uint32_t*)(g_ol + ro0 + nt*8) = lv;
        bsplit(hv, lv, o[nt][2]*inv1, o[nt][3]*inv1);
        *(uint32_t*)(g_oh + ro1 + nt*8) = hv;
        *(uint32_t*)(g_ol + ro1 + nt*8) = lv;
    }
#undef AISSUE
}

// ---------------- launch -----------------------------------------------------
extern "C" void kernel_launch(void* const* d_in, const int* in_sizes, int n_in,
                              void* d_out, int out_size) {
    const float* X   = (const float*)d_in[0];
    const float* Wq  = (const float*)d_in[1];
    const float* Wk  = (const float*)d_in[2];
    const float* Wv  = (const float*)d_in[3];
    const float* Wo  = (const float*)d_in[4];
    const float* rel = (const float*)d_in[5];
    float* out = (float*)d_out;

    cudaFuncSetAttribute(gemm_mma, cudaFuncAttributeMaxDynamicSharedMemorySize, G_SMEM);
    cudaFuncSetAttribute(attn_mma, cudaFuncAttributeMaxDynamicSharedMemorySize, 2*AT_STG);

    bias_kernel<<<16, 256>>>(rel);
    conv_split<<<4096, 256>>>((const float4*)X);
    conv_wT<<<dim3(32, 32, 4), dim3(32, 8)>>>(Wq, Wk, Wv, Wo);

    gemm_mma<<<dim3(24, 32), 256, G_SMEM>>>(1, nullptr);   // fused QKV

    attn_mma<<<dim3(SEQ/128, BATCH*NH), 256, 2*AT_STG>>>();

    gemm_mma<<<dim3(8, 32), 256, G_SMEM>>>(0, out);        // O projection
}

// round 15
// speedup vs baseline: 1.7632x; 1.2037x over previous
#include <cuda_runtime.h>
#include <cuda_bf16.h>
#include <cuda_fp16.h>
#include <math.h>
#include <stdint.h>

#define NH   16
#define DH   64
#define SEQ  2048
#define BATCH 2
#define DM   1024
#define MROWS (BATCH*SEQ)   // 4096

__device__ __forceinline__ uint32_t smem_u32(const void* p) {
    uint32_t a;
    asm("{ .reg .u64 t; cvta.to.shared.u64 t, %1; cvt.u32.u64 %0, t; }"
        : "=r"(a) : "l"(p));
    return a;
}
__device__ __forceinline__ void cpa16(uint32_t s, const void* g) {
    asm volatile("cp.async.cg.shared.global [%0], [%1], 16;" :: "r"(s), "l"(g));
}
__device__ __forceinline__ void ldsm4(uint32_t r[4], uint32_t a) {
    asm volatile("ldmatrix.sync.aligned.m8n8.x4.shared.b16 {%0,%1,%2,%3}, [%4];"
                 : "=r"(r[0]), "=r"(r[1]), "=r"(r[2]), "=r"(r[3]) : "r"(a));
}
// bf16 mma
__device__ __forceinline__ void mma16816(float c[4], const uint32_t a[4],
                                         const uint32_t b0, const uint32_t b1) {
    asm volatile("mma.sync.aligned.m16n8k16.row.col.f32.bf16.bf16.f32 "
        "{%0,%1,%2,%3}, {%4,%5,%6,%7}, {%8,%9}, {%0,%1,%2,%3};"
        : "+f"(c[0]), "+f"(c[1]), "+f"(c[2]), "+f"(c[3])
        : "r"(a[0]), "r"(a[1]), "r"(a[2]), "r"(a[3]), "r"(b0), "r"(b1));
}
// fp16 mma
__device__ __forceinline__ void mma16816h(float c[4], const uint32_t a[4],
                                          const uint32_t b0, const uint32_t b1) {
    asm volatile("mma.sync.aligned.m16n8k16.row.col.f32.f16.f16.f32 "
        "{%0,%1,%2,%3}, {%4,%5,%6,%7}, {%8,%9}, {%0,%1,%2,%3};"
        : "+f"(c[0]), "+f"(c[1]), "+f"(c[2]), "+f"(c[3])
        : "r"(a[0]), "r"(a[1]), "r"(a[2]), "r"(a[3]), "r"(b0), "r"(b1));
}
__device__ __forceinline__ uint32_t cvt2(float x, float y) {   // bf16x2, lo=x
    uint32_t r; asm("cvt.rn.bf16x2.f32 %0, %1, %2;" : "=r"(r) : "f"(y), "f"(x));
    return r;
}
__device__ __forceinline__ void bsplit(uint32_t &hi, uint32_t &lo, float x, float y) {
    uint32_t h = cvt2(x, y);
    float xr = x - __uint_as_float(h << 16);
    float yr = y - __uint_as_float(h & 0xffff0000u);
    hi = h; lo = cvt2(xr, yr);
}
__device__ __forceinline__ uint32_t pkh2(float x, float y) {   // fp16x2, lo=x
    __half2 t = __floats2half2_rn(x, y);
    return *(uint32_t*)&t;
}
__device__ __forceinline__ void hsplit(uint32_t &hi, uint32_t &lo, float x, float y) {
    __half hx = __float2half_rn(x), hy = __float2half_rn(y);
    hi = pkh2(__half2float(hx), __half2float(hy));   // exact repack
    __half2 t = __halves2half2(hx, hy);
    hi = *(uint32_t*)&t;
    lo = pkh2(x - __half2float(hx), y - __half2float(hy));
}

// ---------------- scratch (device globals; no allocations allowed) ----------
__device__ float g_bias[NH*4096];                      // [h][rel+2047]
__device__ __nv_bfloat16 g_xh[(size_t)MROWS*DM];       // X hi (bf16)
__device__ __nv_bfloat16 g_xl[(size_t)MROWS*DM];       // X lo
__device__ __half        g_of[(size_t)MROWS*DM];       // attn-out (fp16 single)
__device__ __nv_bfloat16 g_wth[4*(size_t)DM*DM];       // W^T hi [w][n][k] (w3 = fp16 bits)
__device__ __nv_bfloat16 g_wtl[4*(size_t)DM*DM];       // W^T lo
__device__ __nv_bfloat16 g_qh[(size_t)BATCH*NH*SEQ*DH];  // Q hi [b,h,s,d] bf16
__device__ __nv_bfloat16 g_ql[(size_t)BATCH*NH*SEQ*DH];
__device__ __nv_bfloat16 g_kh[(size_t)BATCH*NH*SEQ*DH];  // K hi [b,h,s,d] bf16
__device__ __nv_bfloat16 g_kl[(size_t)BATCH*NH*SEQ*DH];
__device__ __half        g_vh[(size_t)BATCH*NH*DH*SEQ];  // V hi [b,h,d,s] fp16
__device__ __half        g_vl[(size_t)BATCH*NH*DH*SEQ];  // V lo fp16

// ---------------- relative-position bias table ------------------------------
__global__ void bias_kernel(const float* __restrict__ rel_emb) {
    int idx = blockIdx.x * blockDim.x + threadIdx.x;   // 0..4094
    if (idx >= 4095) return;
    int rel = idx - 2047;
    int bucket = (rel > 0) ? 16 : 0;
    int r = abs(rel);
    int bval;
    if (r < 8) bval = r;
    else {
        float v = logf((float)r / 8.0f) / 2.772588722239781f * 8.0f;
        bval = min(8 + (int)v, 15);
    }
    bucket += bval;
#pragma unroll
    for (int h = 0; h < NH; h++)
        g_bias[h*4096 + idx] = rel_emb[bucket*NH + h];
}

// ---------------- fp32 -> bf16 hi/lo split of X -----------------------------
__global__ void conv_split(const float4* __restrict__ src) {
    int i = blockIdx.x * blockDim.x + threadIdx.x;    // 1048576
    float4 v = src[i];
    uint32_t h0, l0, h1, l1;
    bsplit(h0, l0, v.x, v.y);
    bsplit(h1, l1, v.z, v.w);
    ((uint32_t*)g_xh)[2*i] = h0; ((uint32_t*)g_xh)[2*i+1] = h1;
    ((uint32_t*)g_xl)[2*i] = l0; ((uint32_t*)g_xl)[2*i+1] = l1;
}

// ---------------- weight transpose + split: W[K][N] -> W^T[N][K] ------------
// z<3: bf16 hi/lo.  z==3 (Wo): fp16 hi/lo (bit-stored in same arrays).
__global__ void conv_wT(const float* __restrict__ W0, const float* __restrict__ W1,
                        const float* __restrict__ W2, const float* __restrict__ W3) {
    __shared__ float t[32][33];
    int z = blockIdx.z;
    const float* W = (z == 0) ? W0 : (z == 1) ? W1 : (z == 2) ? W2 : W3;
    __nv_bfloat16* oh = g_wth + (size_t)z*DM*DM;
    __nv_bfloat16* ol = g_wtl + (size_t)z*DM*DM;
    int k0 = blockIdx.y*32, n0 = blockIdx.x*32;
    int tx = threadIdx.x, ty = threadIdx.y;   // (32, 8)
#pragma unroll
    for (int j = 0; j < 4; j++)
        t[tx][ty + 8*j] = W[(size_t)(k0 + ty + 8*j)*DM + n0 + tx];
    __syncthreads();
#pragma unroll
    for (int j = 0; j < 4; j++) {
        float v = t[ty + 8*j][tx];
        size_t o = (size_t)(n0 + ty + 8*j)*DM + k0 + tx;
        if (z < 3) {
            __nv_bfloat16 h = __float2bfloat16(v);
            __nv_bfloat16 l = __float2bfloat16(v - __bfloat162float(h));
            oh[o] = h; ol[o] = l;
        } else {
            __half h = __float2half_rn(v);
            __half l = __float2half_rn(v - __half2float(h));
            *(__half*)&oh[o] = h; *(__half*)&ol[o] = l;
        }
    }
}

// ---------------- warp-MMA GEMM -----------------------------------
// CTA 128x128, 8 warps 64x32, K chunk 32, 3-stage single-barrier pipeline.
// fused=1: QKV bf16 3-pass, grid (24,32), wsel=bx>>3, outputs Q/K bf16, V fp16.
// fused=0: O-proj fp16 2-pass (A=g_of single, B=Wo fp16 hi/lo), fp32 out.
#define AST    32768
#define OFF_AH 0
#define OFF_AL 8192
#define OFF_BH 16384
#define OFF_BL 24576
#define G_SMEM (3*AST)          // 98304

__global__ __launch_bounds__(256) void gemm_mma(int fused, float* __restrict__ Cext) {
    extern __shared__ __align__(16) char sm[];
    uint32_t sb = smem_u32(sm);
    const int tid = threadIdx.x, lane = tid & 31, w = tid >> 5;
    const int wm = w >> 2, wn = w & 3;
    const int by = blockIdx.y;

    int wsel, bxx, cmode;
    if (fused) { wsel = blockIdx.x >> 3; bxx = blockIdx.x & 7; cmode = wsel; }
    else       { wsel = 3; bxx = blockIdx.x; cmode = 3; }

    const char* Ah = fused ? (const char*)(g_xh + (size_t)(by*128)*DM)
                           : (const char*)(g_of + (size_t)(by*128)*DM);
    const char* Al = (const char*)(g_xl + (size_t)(by*128)*DM);
    const char* Bh = (const char*)(g_wth + (size_t)wsel*DM*DM + (size_t)(bxx*128)*DM);
    const char* Bl = (const char*)(g_wtl + (size_t)wsel*DM*DM + (size_t)(bxx*128)*DM);

    const int lr  = tid >> 2;
    const int blk = tid & 3;

    float acc[4][4][4];
#pragma unroll
    for (int mt = 0; mt < 4; mt++)
#pragma unroll
        for (int nt = 0; nt < 4; nt++)
#pragma unroll
            for (int e = 0; e < 4; e++) acc[mt][nt][e] = 0.f;

    uint32_t aRow[4], aXr[4], bRow[2], bXr[2];
#pragma unroll
    for (int mt = 0; mt < 4; mt++) {
        int row = wm*64 + mt*16 + (lane & 15);
        aRow[mt] = (uint32_t)row * 64;
        aXr[mt]  = (uint32_t)((row >> 1) & 3);
    }
    {
        int br0 = wn*32 + (lane & 7) + ((lane >> 4) & 1) * 8;
        int br1 = br0 + 16;
        bRow[0] = (uint32_t)br0 * 64; bXr[0] = (uint32_t)((br0 >> 1) & 3);
        bRow[1] = (uint32_t)br1 * 64; bXr[1] = (uint32_t)((br1 >> 1) & 3);
    }
    const uint32_t cbiA = (uint32_t)(lane >> 4);
    const uint32_t cbiB = (uint32_t)((lane >> 3) & 1);

#define ISSUE(c) do {                                                          \
    uint32_t stb_ = sb + ((c) % 3) * AST;                                      \
    int kofs_ = ((c)*32 + blk*8) * 2;   /* bytes */                            \
    _Pragma("unroll")                                                          \
    for (int half = 0; half < 2; half++) {                                     \
        int r_ = lr + half*64;                                                 \
        uint32_t so_ = (uint32_t)r_*64 + (((uint32_t)blk ^ ((r_>>1)&3))*16);   \
        size_t go_ = (size_t)r_*DM*2 + kofs_;                                  \
        cpa16(stb_ + OFF_AH + so_, Ah + go_);                                  \
        if (fused) cpa16(stb_ + OFF_AL + so_, Al + go_);                       \
        cpa16(stb_ + OFF_BH + so_, Bh + go_);                                  \
        cpa16(stb_ + OFF_BL + so_, Bl + go_);                                  \
    }                                                                          \
    asm volatile("cp.async.commit_group;" ::: "memory");                       \
} while (0)

    ISSUE(0);
    ISSUE(1);

    for (int c = 0; c < 32; c++) {
        if (c < 31) asm volatile("cp.async.wait_group 1;" ::: "memory");
        else        asm volatile("cp.async.wait_group 0;" ::: "memory");
        __syncthreads();
        if (c < 30) ISSUE(c + 2);

        uint32_t stb = sb + (c % 3) * AST;
#pragma unroll
        for (int s = 0; s < 2; s++) {
            uint32_t ah[4][4], al[4][4], bh[2][4], bl[2][4];
            uint32_t bA = 2*s + cbiA;
            uint32_t bB = 2*s + cbiB;
#pragma unroll
            for (int mt = 0; mt < 4; mt++) {
                uint32_t off = aRow[mt] + ((bA ^ aXr[mt]) << 4);
                ldsm4(ah[mt], stb + OFF_AH + off);
                if (fused) ldsm4(al[mt], stb + OFF_AL + off);
            }
#pragma unroll
            for (int p = 0; p < 2; p++) {
                uint32_t off = bRow[p] + ((bB ^ bXr[p]) << 4);
                ldsm4(bh[p], stb + OFF_BH + off);
                ldsm4(bl[p], stb + OFF_BL + off);
            }
            if (fused) {
                // bf16 3-pass
#pragma unroll
                for (int mt = 0; mt < 4; mt++)
#pragma unroll
                    for (int nt = 0; nt < 4; nt++) {
                        const uint32_t* bth = bh[nt >> 1] + (nt & 1) * 2;
                        mma16816(acc[mt][nt], ah[mt], bth[0], bth[1]);
                    }
#pragma unroll
                for (int mt = 0; mt < 4; mt++)
#pragma unroll
                    for (int nt = 0; nt < 4; nt++) {
                        const uint32_t* btl = bl[nt >> 1] + (nt & 1) * 2;
                        mma16816(acc[mt][nt], ah[mt], btl[0], btl[1]);
                    }
#pragma unroll
                for (int mt = 0; mt < 4; mt++)
#pragma unroll
                    for (int nt = 0; nt < 4; nt++) {
                        const uint32_t* bth = bh[nt >> 1] + (nt & 1) * 2;
                        mma16816(acc[mt][nt], al[mt], bth[0], bth[1]);
                    }
            } else {
                // fp16 2-pass (A single)
#pragma unroll
                for (int mt = 0; mt < 4; mt++)
#pragma unroll
                    for (int nt = 0; nt < 4; nt++) {
                        const uint32_t* bth = bh[nt >> 1] + (nt & 1) * 2;
                        mma16816h(acc[mt][nt], ah[mt], bth[0], bth[1]);
                    }
#pragma unroll
                for (int mt = 0; mt < 4; mt++)
#pragma unroll
                    for (int nt = 0; nt < 4; nt++) {
                        const uint32_t* btl = bl[nt >> 1] + (nt & 1) * 2;
                        mma16816h(acc[mt][nt], ah[mt], btl[0], btl[1]);
                    }
            }
        }
    }
    __syncthreads();

    float (*Cs)[136] = (float (*)[136])sm;
#pragma unroll
    for (int mt = 0; mt < 4; mt++)
#pragma unroll
        for (int nt = 0; nt < 4; nt++) {
            int row = wm*64 + mt*16 + (lane >> 2);
            int col = wn*32 + nt*8 + 2*(lane & 3);
            Cs[row    ][col] = acc[mt][nt][0]; Cs[row    ][col+1] = acc[mt][nt][1];
            Cs[row + 8][col] = acc[mt][nt][2]; Cs[row + 8][col+1] = acc[mt][nt][3];
        }
    __syncthreads();

    int b = by >> 4;
    if (cmode == 3) {
        int mr = tid >> 1, half = tid & 1;
        const float* src = &Cs[mr][half*64];
        float* dst = Cext + (size_t)(by*128 + mr)*DM + bxx*128 + half*64;
#pragma unroll
        for (int j = 0; j < 16; j++)
            ((float4*)dst)[j] = ((const float4*)src)[j];
    } else if (cmode <= 1) {
        int mr = tid >> 1, half = tid & 1;
        int hh = bxx*2 + half;
        int s  = (by & 15)*128 + mr;
        __nv_bfloat16* DST_H = cmode ? g_kh : g_qh;
        __nv_bfloat16* DST_L = cmode ? g_kl : g_ql;
        size_t base = ((size_t)(b*NH + hh)*SEQ + s)*DH;
        const float* src = &Cs[mr][half*64];
#pragma unroll
        for (int j8 = 0; j8 < 8; j8++) {
            uint32_t hv[4], lv[4];
#pragma unroll
            for (int e = 0; e < 4; e++)
                bsplit(hv[e], lv[e], src[j8*8 + 2*e], src[j8*8 + 2*e + 1]);
            *(uint4*)(DST_H + base + j8*8) = make_uint4(hv[0], hv[1], hv[2], hv[3]);
            *(uint4*)(DST_L + base + j8*8) = make_uint4(lv[0], lv[1], lv[2], lv[3]);
        }
    } else {
        // V: fp16 hi/lo, [b,h,d,s]
        int d_idx = tid >> 5;
        int s4    = (tid & 31) * 4;
        int sg    = (by & 15)*128 + s4;
#pragma unroll
        for (int dd = 0; dd < 16; dd++) {
            int d = dd*8 + d_idx;
            int n = bxx*128 + d;
            int hh = n >> 6, dg = n & 63;
            uint32_t h0, l0, h1, l1;
            hsplit(h0, l0, Cs[s4][d],   Cs[s4+1][d]);
            hsplit(h1, l1, Cs[s4+2][d], Cs[s4+3][d]);
            size_t base = ((size_t)(b*NH + hh)*DH + dg)*SEQ + sg;
            *(uint2*)(g_vh + base) = make_uint2(h0, h1);
            *(uint2*)(g_vl + base) = make_uint2(l0, l1);
        }
    }
#undef ISSUE
}

// ---------------- flash attention: S bf16 3-pass, PV fp16 2-pass ------------
// R11 structure: 64q/CTA, 128 thr, 2-stage, 3 CTAs/SM.
#define AT_STG 32768
__global__ __launch_bounds__(128, 3) void attn_mma() {
    extern __shared__ __align__(16) char asmem[];
    uint32_t sb = smem_u32(asmem);
    const int tid = threadIdx.x, lane = tid & 31, w = tid >> 5;
    const int bh = blockIdx.y, h = bh & (NH-1), b = bh >> 4;
    const int q0 = blockIdx.x * 64;
    const int lr8 = lane & 7, lg = lane >> 3;
    const int r0 = w*16 + (lane >> 2);
    const int qc = 2*(lane & 3);

    const __nv_bfloat16* Qh_g = g_qh + ((size_t)bh*SEQ + q0)*DH;
    const __nv_bfloat16* Ql_g = g_ql + ((size_t)bh*SEQ + q0)*DH;
    const __nv_bfloat16* Kh_g = g_kh + (size_t)bh*SEQ*DH;
    const __nv_bfloat16* Kl_g = g_kl + (size_t)bh*SEQ*DH;
    const __half* Vh_g = g_vh + (size_t)bh*DH*SEQ;
    const __half* Vl_g = g_vl + (size_t)bh*DH*SEQ;
    const float* biasrow = g_bias + h*4096;

    uint32_t aqh[4][4], aql[4][4];
#pragma unroll
    for (int kt = 0; kt < 4; kt++) {
        int c0 = kt*16 + qc;
        aqh[kt][0] = *(const uint32_t*)(Qh_g + (size_t)r0*DH + c0);
        aqh[kt][1] = *(const uint32_t*)(Qh_g + (size_t)(r0+8)*DH + c0);
        aqh[kt][2] = *(const uint32_t*)(Qh_g + (size_t)r0*DH + c0 + 8);
        aqh[kt][3] = *(const uint32_t*)(Qh_g + (size_t)(r0+8)*DH + c0 + 8);
        aql[kt][0] = *(const uint32_t*)(Ql_g + (size_t)r0*DH + c0);
        aql[kt][1] = *(const uint32_t*)(Ql_g + (size_t)(r0+8)*DH + c0);
        aql[kt][2] = *(const uint32_t*)(Ql_g + (size_t)r0*DH + c0 + 8);
        aql[kt][3] = *(const uint32_t*)(Ql_g + (size_t)(r0+8)*DH + c0 + 8);
    }

    float o[8][4];
#pragma unroll
    for (int nt = 0; nt < 8; nt++)
#pragma unroll
        for (int e = 0; e < 4; e++) o[nt][e] = 0.f;
    float m0 = -1e30f, m1 = -1e30f, l0 = 0.f, l1 = 0.f;

#define AISSUE(it_) do {                                                        \
    int k0_ = (it_)*64;                                                         \
    uint32_t stb_ = sb + ((it_) & 1)*AT_STG;                                    \
    _Pragma("unroll")                                                           \
    for (int i_ = 0; i_ < 16; i_++) {                                           \
        int id_ = tid + i_*128;                                                 \
        int arr_ = id_ >> 9, rem_ = id_ & 511, row_ = rem_ >> 3, bk_ = rem_ & 7;\
        uint32_t dst_ = stb_ + arr_*8192 + row_*128 + ((bk_ ^ (row_ & 7))*16);  \
        const void* src_;                                                       \
        if (arr_ == 0)      src_ = Kh_g + (size_t)(k0_ + row_)*DH + bk_*8;      \
        else if (arr_ == 1) src_ = Kl_g + (size_t)(k0_ + row_)*DH + bk_*8;      \
        else if (arr_ == 2) src_ = Vh_g + (size_t)row_*SEQ + k0_ + bk_*8;       \
        else                src_ = Vl_g + (size_t)row_*SEQ + k0_ + bk_*8;       \
        cpa16(dst_, src_);                                                      \
    }                                                                           \
    asm volatile("cp.async.commit_group;" ::: "memory");                        \
} while (0)

    AISSUE(0);
    AISSUE(1);

    for (int it = 0; it < 32; it++) {
        if (it < 31) asm volatile("cp.async.wait_group 1;" ::: "memory");
        else         asm volatile("cp.async.wait_group 0;" ::: "memory");
        __syncthreads();
        uint32_t stg = sb + (it & 1)*AT_STG;

        // ---- S = Q K^T (bf16 3-pass, pass-outer)
        float sc[8][4];
#pragma unroll
        for (int nt = 0; nt < 8; nt++)
#pragma unroll
            for (int e = 0; e < 4; e++) sc[nt][e] = 0.f;

#pragma unroll
        for (int kt = 0; kt < 4; kt++) {
            uint32_t kh[4][4], kl[4][4];
#pragma unroll
            for (int nb = 0; nb < 4; nb++) {
                int row = nb*16 + lr8 + (lg >> 1)*8;
                int bk  = 2*kt + (lg & 1);
                uint32_t ad = stg + row*128 + ((bk ^ (row & 7))*16);
                ldsm4(kh[nb], ad);
                ldsm4(kl[nb], ad + 8192);
            }
#pragma unroll
            for (int nb = 0; nb < 4; nb++) {
                mma16816(sc[2*nb],   aqh[kt], kh[nb][0], kh[nb][1]);
                mma16816(sc[2*nb+1], aqh[kt], kh[nb][2], kh[nb][3]);
            }
#pragma unroll
            for (int nb = 0; nb < 4; nb++) {
                mma16816(sc[2*nb],   aqh[kt], kl[nb][0], kl[nb][1]);
                mma16816(sc[2*nb+1], aqh[kt], kl[nb][2], kl[nb][3]);
            }
#pragma unroll
            for (int nb = 0; nb < 4; nb++) {
                mma16816(sc[2*nb],   aql[kt], kh[nb][0], kh[nb][1]);
                mma16816(sc[2*nb+1], aql[kt], kh[nb][2], kh[nb][3]);
            }
        }

        {
            int relb = it*64 + qc - (q0 + r0) + 2047;
            float bb0[9], bb1[9];
#pragma unroll
            for (int t = 0; t < 9; t++) {
                bb0[t] = biasrow[relb - 8 + t*8];
                bb1[t] = biasrow[relb - 7 + t*8];
            }
#pragma unroll
            for (int nt = 0; nt < 8; nt++) {
                sc[nt][0] += bb0[nt+1]; sc[nt][1] += bb1[nt+1];
                sc[nt][2] += bb0[nt];   sc[nt][3] += bb1[nt];
            }
        }

        float mx0 = sc[0][0], mx1 = sc[0][2];
#pragma unroll
        for (int nt = 0; nt < 8; nt++) {
            mx0 = fmaxf(mx0, fmaxf(sc[nt][0], sc[nt][1]));
            mx1 = fmaxf(mx1, fmaxf(sc[nt][2], sc[nt][3]));
        }
        mx0 = fmaxf(mx0, __shfl_xor_sync(0xffffffffu, mx0, 1));
        mx0 = fmaxf(mx0, __shfl_xor_sync(0xffffffffu, mx0, 2));
        mx1 = fmaxf(mx1, __shfl_xor_sync(0xffffffffu, mx1, 1));
        mx1 = fmaxf(mx1, __shfl_xor_sync(0xffffffffu, mx1, 2));
        float m0n = fmaxf(m0, mx0), m1n = fmaxf(m1, mx1);
        float c0 = __expf(m0 - m0n), c1 = __expf(m1 - m1n);
        m0 = m0n; m1 = m1n;
        float s0 = 0.f, s1 = 0.f;
#pragma unroll
        for (int nt = 0; nt < 8; nt++) {
            sc[nt][0] = __expf(sc[nt][0] - m0n);
            sc[nt][1] = __expf(sc[nt][1] - m0n);
            sc[nt][2] = __expf(sc[nt][2] - m1n);
            sc[nt][3] = __expf(sc[nt][3] - m1n);
            s0 += sc[nt][0] + sc[nt][1];
            s1 += sc[nt][2] + sc[nt][3];
        }
        s0 += __shfl_xor_sync(0xffffffffu, s0, 1);
        s0 += __shfl_xor_sync(0xffffffffu, s0, 2);
        s1 += __shfl_xor_sync(0xffffffffu, s1, 1);
        s1 += __shfl_xor_sync(0xffffffffu, s1, 2);
        l0 = l0*c0 + s0; l1 = l1*c1 + s1;
#pragma unroll
        for (int nt = 0; nt < 8; nt++) {
            o[nt][0] *= c0; o[nt][1] *= c0;
            o[nt][2] *= c1; o[nt][3] *= c1;
        }

        // ---- O += P V (fp16 2-pass: P single, V hi/lo)
#pragma unroll
        for (int kt = 0; kt < 4; kt++) {
            uint32_t pf[4];
            pf[0] = pkh2(sc[2*kt][0],   sc[2*kt][1]);
            pf[1] = pkh2(sc[2*kt][2],   sc[2*kt][3]);
            pf[2] = pkh2(sc[2*kt+1][0], sc[2*kt+1][1]);
            pf[3] = pkh2(sc[2*kt+1][2], sc[2*kt+1][3]);
            uint32_t vh[4][4], vl[4][4];
#pragma unroll
            for (int nb = 0; nb < 4; nb++) {
                int row = nb*16 + lr8 + (lg >> 1)*8;
                int bk  = 2*kt + (lg & 1);
                uint32_t ad = stg + 16384 + row*128 + ((bk ^ (row & 7))*16);
                ldsm4(vh[nb], ad);
                ldsm4(vl[nb], ad + 8192);
            }
#pragma unroll
            for (int nb = 0; nb < 4; nb++) {
                mma16816h(o[2*nb],   pf, vh[nb][0], vh[nb][1]);
                mma16816h(o[2*nb+1], pf, vh[nb][2], vh[nb][3]);
            }
#pragma unroll
            for (int nb = 0; nb < 4; nb++) {
                mma16816h(o[2*nb],   pf, vl[nb][0], vl[nb][1]);
                mma16816h(o[2*nb+1], pf, vl[nb][2], vl[nb][3]);
            }
        }
        __syncthreads();
        if (it + 2 < 32) AISSUE(it + 2);
    }

    // normalize + store single fp16 to g_of [b,s,h*64+d]
    float inv0 = 1.0f / l0, inv1 = 1.0f / l1;
    size_t ro0 = ((size_t)b*SEQ + q0 + r0)*DM + h*DH + qc;
    size_t ro1 = ro0 + (size_t)8*DM;
#pragma unroll
    for (int nt = 0; nt < 8; nt++) {
        *(uint32_t*)(g_of + ro0 + nt*8) = pkh2(o[nt][0]*inv0, o[nt][1]*inv0);
        *(uint32_t*)(g_of + ro1 + nt*8) = pkh2(o[nt][2]*inv1, o[nt][3]*inv1);
    }
#undef AISSUE
}

// ---------------- launch -----------------------------------------------------
extern "C" void kernel_launch(void* const* d_in, const int* in_sizes, int n_in,
                              void* d_out, int out_size) {
    const float* X   = (const float*)d_in[0];
    const float* Wq  = (const float*)d_in[1];
    const float* Wk  = (const float*)d_in[2];
    const float* Wv  = (const float*)d_in[3];
    const float* Wo  = (const float*)d_in[4];
    const float* rel = (const float*)d_in[5];
    float* out = (float*)d_out;

    cudaFuncSetAttribute(gemm_mma, cudaFuncAttributeMaxDynamicSharedMemorySize, G_SMEM);
    cudaFuncSetAttribute(attn_mma, cudaFuncAttributeMaxDynamicSharedMemorySize, 2*AT_STG);

    bias_kernel<<<16, 256>>>(rel);
    conv_split<<<4096, 256>>>((const float4*)X);
    conv_wT<<<dim3(32, 32, 4), dim3(32, 8)>>>(Wq, Wk, Wv, Wo);

    gemm_mma<<<dim3(24, 32), 256, G_SMEM>>>(1, nullptr);   // fused QKV (bf16 3-pass)

    attn_mma<<<dim3(SEQ/64, BATCH*NH), 128, 2*AT_STG>>>();

    gemm_mma<<<dim3(8, 32), 256, G_SMEM>>>(0, out);        // O proj (fp16 2-pass)
}

// round 16
// speedup vs baseline: 1.8755x; 1.0637x over previous
#include <cuda_runtime.h>
#include <cuda_bf16.h>
#include <cuda_fp16.h>
#include <math.h>
#include <stdint.h>

#define NH   16
#define DH   64
#define SEQ  2048
#define BATCH 2
#define DM   1024
#define MROWS (BATCH*SEQ)   // 4096

__device__ __forceinline__ uint32_t smem_u32(const void* p) {
    uint32_t a;
    asm("{ .reg .u64 t; cvta.to.shared.u64 t, %1; cvt.u32.u64 %0, t; }"
        : "=r"(a) : "l"(p));
    return a;
}
__device__ __forceinline__ void cpa16(uint32_t s, const void* g) {
    asm volatile("cp.async.cg.shared.global [%0], [%1], 16;" :: "r"(s), "l"(g));
}
__device__ __forceinline__ void ldsm4(uint32_t r[4], uint32_t a) {
    asm volatile("ldmatrix.sync.aligned.m8n8.x4.shared.b16 {%0,%1,%2,%3}, [%4];"
                 : "=r"(r[0]), "=r"(r[1]), "=r"(r[2]), "=r"(r[3]) : "r"(a));
}
// bf16 mma
__device__ __forceinline__ void mma16816(float c[4], const uint32_t a[4],
                                         const uint32_t b0, const uint32_t b1) {
    asm volatile("mma.sync.aligned.m16n8k16.row.col.f32.bf16.bf16.f32 "
        "{%0,%1,%2,%3}, {%4,%5,%6,%7}, {%8,%9}, {%0,%1,%2,%3};"
        : "+f"(c[0]), "+f"(c[1]), "+f"(c[2]), "+f"(c[3])
        : "r"(a[0]), "r"(a[1]), "r"(a[2]), "r"(a[3]), "r"(b0), "r"(b1));
}
// fp16 mma
__device__ __forceinline__ void mma16816h(float c[4], const uint32_t a[4],
                                          const uint32_t b0, const uint32_t b1) {
    asm volatile("mma.sync.aligned.m16n8k16.row.col.f32.f16.f16.f32 "
        "{%0,%1,%2,%3}, {%4,%5,%6,%7}, {%8,%9}, {%0,%1,%2,%3};"
        : "+f"(c[0]), "+f"(c[1]), "+f"(c[2]), "+f"(c[3])
        : "r"(a[0]), "r"(a[1]), "r"(a[2]), "r"(a[3]), "r"(b0), "r"(b1));
}
__device__ __forceinline__ uint32_t cvt2(float x, float y) {   // bf16x2, lo=x
    uint32_t r; asm("cvt.rn.bf16x2.f32 %0, %1, %2;" : "=r"(r) : "f"(y), "f"(x));
    return r;
}
__device__ __forceinline__ void bsplit(uint32_t &hi, uint32_t &lo, float x, float y) {
    uint32_t h = cvt2(x, y);
    float xr = x - __uint_as_float(h << 16);
    float yr = y - __uint_as_float(h & 0xffff0000u);
    hi = h; lo = cvt2(xr, yr);
}
__device__ __forceinline__ uint32_t pkh2(float x, float y) {   // fp16x2, lo=x
    __half2 t = __floats2half2_rn(x, y);
    return *(uint32_t*)&t;
}

// ---------------- scratch (device globals; no allocations allowed) ----------
__device__ float g_bias[NH*4096];                      // [h][rel+2047]
__device__ __nv_bfloat16 g_xh[(size_t)MROWS*DM];       // X hi (bf16)
__device__ __nv_bfloat16 g_xl[(size_t)MROWS*DM];       // X lo
__device__ __half        g_of[(size_t)MROWS*DM];       // attn-out (fp16 single)
__device__ __nv_bfloat16 g_wth[4*(size_t)DM*DM];       // W^T hi [w][n][k] (w3 = fp16 bits)
__device__ __nv_bfloat16 g_wtl[4*(size_t)DM*DM];       // W^T lo
__device__ __nv_bfloat16 g_qh[(size_t)BATCH*NH*SEQ*DH];  // Q hi [b,h,s,d] bf16
__device__ __nv_bfloat16 g_ql[(size_t)BATCH*NH*SEQ*DH];
__device__ __nv_bfloat16 g_kh[(size_t)BATCH*NH*SEQ*DH];  // K hi [b,h,s,d] bf16
__device__ __nv_bfloat16 g_kl[(size_t)BATCH*NH*SEQ*DH];
__device__ __half        g_vh[(size_t)BATCH*NH*DH*SEQ];  // V [b,h,d,s] fp16 single

// ---------------- relative-position bias table ------------------------------
__global__ void bias_kernel(const float* __restrict__ rel_emb) {
    int idx = blockIdx.x * blockDim.x + threadIdx.x;   // 0..4094
    if (idx >= 4095) return;
    int rel = idx - 2047;
    int bucket = (rel > 0) ? 16 : 0;
    int r = abs(rel);
    int bval;
    if (r < 8) bval = r;
    else {
        float v = logf((float)r / 8.0f) / 2.772588722239781f * 8.0f;
        bval = min(8 + (int)v, 15);
    }
    bucket += bval;
#pragma unroll
    for (int h = 0; h < NH; h++)
        g_bias[h*4096 + idx] = rel_emb[bucket*NH + h];
}

// ---------------- fp32 -> bf16 hi/lo split of X -----------------------------
__global__ void conv_split(const float4* __restrict__ src) {
    int i = blockIdx.x * blockDim.x + threadIdx.x;    // 1048576
    float4 v = src[i];
    uint32_t h0, l0, h1, l1;
    bsplit(h0, l0, v.x, v.y);
    bsplit(h1, l1, v.z, v.w);
    ((uint32_t*)g_xh)[2*i] = h0; ((uint32_t*)g_xh)[2*i+1] = h1;
    ((uint32_t*)g_xl)[2*i] = l0; ((uint32_t*)g_xl)[2*i+1] = l1;
}

// ---------------- weight transpose + split: W[K][N] -> W^T[N][K] ------------
// z<3: bf16 hi/lo.  z==3 (Wo): fp16 hi/lo (bit-stored in same arrays).
__global__ void conv_wT(const float* __restrict__ W0, const float* __restrict__ W1,
                        const float* __restrict__ W2, const float* __restrict__ W3) {
    __shared__ float t[32][33];
    int z = blockIdx.z;
    const float* W = (z == 0) ? W0 : (z == 1) ? W1 : (z == 2) ? W2 : W3;
    __nv_bfloat16* oh = g_wth + (size_t)z*DM*DM;
    __nv_bfloat16* ol = g_wtl + (size_t)z*DM*DM;
    int k0 = blockIdx.y*32, n0 = blockIdx.x*32;
    int tx = threadIdx.x, ty = threadIdx.y;   // (32, 8)
#pragma unroll
    for (int j = 0; j < 4; j++)
        t[tx][ty + 8*j] = W[(size_t)(k0 + ty + 8*j)*DM + n0 + tx];
    __syncthreads();
#pragma unroll
    for (int j = 0; j < 4; j++) {
        float v = t[ty + 8*j][tx];
        size_t o = (size_t)(n0 + ty + 8*j)*DM + k0 + tx;
        if (z < 3) {
            __nv_bfloat16 h = __float2bfloat16(v);
            __nv_bfloat16 l = __float2bfloat16(v - __bfloat162float(h));
            oh[o] = h; ol[o] = l;
        } else {
            __half h = __float2half_rn(v);
            __half l = __float2half_rn(v - __half2float(h));
            *(__half*)&oh[o] = h; *(__half*)&ol[o] = l;
        }
    }
}

// ---------------- warp-MMA GEMM -----------------------------------
// CTA 128x128, 8 warps 64x32, K chunk 32, 3-stage single-barrier pipeline.
// fused=1: QKV bf16 3-pass, grid (24,32): Q/K bf16 hi/lo, V fp16 single.
// fused=0: O-proj fp16 2-pass (A=g_of single, B=Wo fp16 hi/lo), fp32 out.
#define AST    32768
#define OFF_AH 0
#define OFF_AL 8192
#define OFF_BH 16384
#define OFF_BL 24576
#define G_SMEM (3*AST)          // 98304

__global__ __launch_bounds__(256) void gemm_mma(int fused, float* __restrict__ Cext) {
    extern __shared__ __align__(16) char sm[];
    uint32_t sb = smem_u32(sm);
    const int tid = threadIdx.x, lane = tid & 31, w = tid >> 5;
    const int wm = w >> 2, wn = w & 3;
    const int by = blockIdx.y;

    int wsel, bxx, cmode;
    if (fused) { wsel = blockIdx.x >> 3; bxx = blockIdx.x & 7; cmode = wsel; }
    else       { wsel = 3; bxx = blockIdx.x; cmode = 3; }

    const char* Ah = fused ? (const char*)(g_xh + (size_t)(by*128)*DM)
                           : (const char*)(g_of + (size_t)(by*128)*DM);
    const char* Al = (const char*)(g_xl + (size_t)(by*128)*DM);
    const char* Bh = (const char*)(g_wth + (size_t)wsel*DM*DM + (size_t)(bxx*128)*DM);
    const char* Bl = (const char*)(g_wtl + (size_t)wsel*DM*DM + (size_t)(bxx*128)*DM);

    const int lr  = tid >> 2;
    const int blk = tid & 3;

    float acc[4][4][4];
#pragma unroll
    for (int mt = 0; mt < 4; mt++)
#pragma unroll
        for (int nt = 0; nt < 4; nt++)
#pragma unroll
            for (int e = 0; e < 4; e++) acc[mt][nt][e] = 0.f;

    uint32_t aRow[4], aXr[4], bRow[2], bXr[2];
#pragma unroll
    for (int mt = 0; mt < 4; mt++) {
        int row = wm*64 + mt*16 + (lane & 15);
        aRow[mt] = (uint32_t)row * 64;
        aXr[mt]  = (uint32_t)((row >> 1) & 3);
    }
    {
        int br0 = wn*32 + (lane & 7) + ((lane >> 4) & 1) * 8;
        int br1 = br0 + 16;
        bRow[0] = (uint32_t)br0 * 64; bXr[0] = (uint32_t)((br0 >> 1) & 3);
        bRow[1] = (uint32_t)br1 * 64; bXr[1] = (uint32_t)((br1 >> 1) & 3);
    }
    const uint32_t cbiA = (uint32_t)(lane >> 4);
    const uint32_t cbiB = (uint32_t)((lane >> 3) & 1);

#define ISSUE(c) do {                                                          \
    uint32_t stb_ = sb + ((c) % 3) * AST;                                      \
    int kofs_ = ((c)*32 + blk*8) * 2;   /* bytes */                            \
    _Pragma("unroll")                                                          \
    for (int half = 0; half < 2; half++) {                                     \
        int r_ = lr + half*64;                                                 \
        uint32_t so_ = (uint32_t)r_*64 + (((uint32_t)blk ^ ((r_>>1)&3))*16);   \
        size_t go_ = (size_t)r_*DM*2 + kofs_;                                  \
        cpa16(stb_ + OFF_AH + so_, Ah + go_);                                  \
        if (fused) cpa16(stb_ + OFF_AL + so_, Al + go_);                       \
        cpa16(stb_ + OFF_BH + so_, Bh + go_);                                  \
        cpa16(stb_ + OFF_BL + so_, Bl + go_);                                  \
    }                                                                          \
    asm volatile("cp.async.commit_group;" ::: "memory");                       \
} while (0)

    ISSUE(0);
    ISSUE(1);

    for (int c = 0; c < 32; c++) {
        if (c < 31) asm volatile("cp.async.wait_group 1;" ::: "memory");
        else        asm volatile("cp.async.wait_group 0;" ::: "memory");
        __syncthreads();
        if (c < 30) ISSUE(c + 2);

        uint32_t stb = sb + (c % 3) * AST;
#pragma unroll
        for (int s = 0; s < 2; s++) {
            uint32_t ah[4][4], al[4][4], bh[2][4], bl[2][4];
            uint32_t bA = 2*s + cbiA;
            uint32_t bB = 2*s + cbiB;
#pragma unroll
            for (int mt = 0; mt < 4; mt++) {
                uint32_t off = aRow[mt] + ((bA ^ aXr[mt]) << 4);
                ldsm4(ah[mt], stb + OFF_AH + off);
                if (fused) ldsm4(al[mt], stb + OFF_AL + off);
            }
#pragma unroll
            for (int p = 0; p < 2; p++) {
                uint32_t off = bRow[p] + ((bB ^ bXr[p]) << 4);
                ldsm4(bh[p], stb + OFF_BH + off);
                ldsm4(bl[p], stb + OFF_BL + off);
            }
            if (fused) {
#pragma unroll
                for (int mt = 0; mt < 4; mt++)
#pragma unroll
                    for (int nt = 0; nt < 4; nt++) {
                        const uint32_t* bth = bh[nt >> 1] + (nt & 1) * 2;
                        mma16816(acc[mt][nt], ah[mt], bth[0], bth[1]);
                    }
#pragma unroll
                for (int mt = 0; mt < 4; mt++)
#pragma unroll
                    for (int nt = 0; nt < 4; nt++) {
                        const uint32_t* btl = bl[nt >> 1] + (nt & 1) * 2;
                        mma16816(acc[mt][nt], ah[mt], btl[0], btl[1]);
                    }
#pragma unroll
                for (int mt = 0; mt < 4; mt++)
#pragma unroll
                    for (int nt = 0; nt < 4; nt++) {
                        const uint32_t* bth = bh[nt >> 1] + (nt & 1) * 2;
                        mma16816(acc[mt][nt], al[mt], bth[0], bth[1]);
                    }
            } else {
#pragma unroll
                for (int mt = 0; mt < 4; mt++)
#pragma unroll
                    for (int nt = 0; nt < 4; nt++) {
                        const uint32_t* bth = bh[nt >> 1] + (nt & 1) * 2;
                        mma16816h(acc[mt][nt], ah[mt], bth[0], bth[1]);
                    }
#pragma unroll
                for (int mt = 0; mt < 4; mt++)
#pragma unroll
                    for (int nt = 0; nt < 4; nt++) {
                        const uint32_t* btl = bl[nt >> 1] + (nt & 1) * 2;
                        mma16816h(acc[mt][nt], ah[mt], btl[0], btl[1]);
                    }
            }
        }
    }
    __syncthreads();

    float (*Cs)[136] = (float (*)[136])sm;
#pragma unroll
    for (int mt = 0; mt < 4; mt++)
#pragma unroll
        for (int nt = 0; nt < 4; nt++) {
            int row = wm*64 + mt*16 + (lane >> 2);
            int col = wn*32 + nt*8 + 2*(lane & 3);
            Cs[row    ][col] = acc[mt][nt][0]; Cs[row    ][col+1] = acc[mt][nt][1];
            Cs[row + 8][col] = acc[mt][nt][2]; Cs[row + 8][col+1] = acc[mt][nt][3];
        }
    __syncthreads();

    int b = by >> 4;
    if (cmode == 3) {
        int mr = tid >> 1, half = tid & 1;
        const float* src = &Cs[mr][half*64];
        float* dst = Cext + (size_t)(by*128 + mr)*DM + bxx*128 + half*64;
#pragma unroll
        for (int j = 0; j < 16; j++)
            ((float4*)dst)[j] = ((const float4*)src)[j];
    } else if (cmode <= 1) {
        int mr = tid >> 1, half = tid & 1;
        int hh = bxx*2 + half;
        int s  = (by & 15)*128 + mr;
        __nv_bfloat16* DST_H = cmode ? g_kh : g_qh;
        __nv_bfloat16* DST_L = cmode ? g_kl : g_ql;
        size_t base = ((size_t)(b*NH + hh)*SEQ + s)*DH;
        const float* src = &Cs[mr][half*64];
#pragma unroll
        for (int j8 = 0; j8 < 8; j8++) {
            uint32_t hv[4], lv[4];
#pragma unroll
            for (int e = 0; e < 4; e++)
                bsplit(hv[e], lv[e], src[j8*8 + 2*e], src[j8*8 + 2*e + 1]);
            *(uint4*)(DST_H + base + j8*8) = make_uint4(hv[0], hv[1], hv[2], hv[3]);
            *(uint4*)(DST_L + base + j8*8) = make_uint4(lv[0], lv[1], lv[2], lv[3]);
        }
    } else {
        // V: fp16 single, [b,h,d,s]
        int d_idx = tid >> 5;
        int s4    = (tid & 31) * 4;
        int sg    = (by & 15)*128 + s4;
#pragma unroll
        for (int dd = 0; dd < 16; dd++) {
            int d = dd*8 + d_idx;
            int n = bxx*128 + d;
            int hh = n >> 6, dg = n & 63;
            uint32_t h0 = pkh2(Cs[s4][d],   Cs[s4+1][d]);
            uint32_t h1 = pkh2(Cs[s4+2][d], Cs[s4+3][d]);
            size_t base = ((size_t)(b*NH + hh)*DH + dg)*SEQ + sg;
            *(uint2*)(g_vh + base) = make_uint2(h0, h1);
        }
    }
#undef ISSUE
}

// ---------------- flash attention: S bf16 3-pass, PV fp16 1-pass ------------
// 64q/CTA, 128 thr, 2-stage (stage: Kh 8K | Kl 8K | V 8K = 24KB), 3 CTAs/SM.
#define AT_STG 24576
__global__ __launch_bounds__(128, 3) void attn_mma() {
    extern __shared__ __align__(16) char asmem[];
    uint32_t sb = smem_u32(asmem);
    const int tid = threadIdx.x, lane = tid & 31, w = tid >> 5;
    const int bh = blockIdx.y, h = bh & (NH-1), b = bh >> 4;
    const int q0 = blockIdx.x * 64;
    const int lr8 = lane & 7, lg = lane >> 3;
    const int r0 = w*16 + (lane >> 2);
    const int qc = 2*(lane & 3);

    const __nv_bfloat16* Qh_g = g_qh + ((size_t)bh*SEQ + q0)*DH;
    const __nv_bfloat16* Ql_g = g_ql + ((size_t)bh*SEQ + q0)*DH;
    const __nv_bfloat16* Kh_g = g_kh + (size_t)bh*SEQ*DH;
    const __nv_bfloat16* Kl_g = g_kl + (size_t)bh*SEQ*DH;
    const __half* Vh_g = g_vh + (size_t)bh*DH*SEQ;
    const float* biasrow = g_bias + h*4096;

    uint32_t aqh[4][4], aql[4][4];
#pragma unroll
    for (int kt = 0; kt < 4; kt++) {
        int c0 = kt*16 + qc;
        aqh[kt][0] = *(const uint32_t*)(Qh_g + (size_t)r0*DH + c0);
        aqh[kt][1] = *(const uint32_t*)(Qh_g + (size_t)(r0+8)*DH + c0);
        aqh[kt][2] = *(const uint32_t*)(Qh_g + (size_t)r0*DH + c0 + 8);
        aqh[kt][3] = *(const uint32_t*)(Qh_g + (size_t)(r0+8)*DH + c0 + 8);
        aql[kt][0] = *(const uint32_t*)(Ql_g + (size_t)r0*DH + c0);
        aql[kt][1] = *(const uint32_t*)(Ql_g + (size_t)(r0+8)*DH + c0);
        aql[kt][2] = *(const uint32_t*)(Ql_g + (size_t)r0*DH + c0 + 8);
        aql[kt][3] = *(const uint32_t*)(Ql_g + (size_t)(r0+8)*DH + c0 + 8);
    }

    float o[8][4];
#pragma unroll
    for (int nt = 0; nt < 8; nt++)
#pragma unroll
        for (int e = 0; e < 4; e++) o[nt][e] = 0.f;
    float m0 = -1e30f, m1 = -1e30f, l0 = 0.f, l1 = 0.f;

#define AISSUE(it_) do {                                                        \
    int k0_ = (it_)*64;                                                         \
    uint32_t stb_ = sb + ((it_) & 1)*AT_STG;                                    \
    _Pragma("unroll")                                                           \
    for (int i_ = 0; i_ < 12; i_++) {                                           \
        int id_ = tid + i_*128;                                                 \
        int arr_ = id_ >> 9, rem_ = id_ & 511, row_ = rem_ >> 3, bk_ = rem_ & 7;\
        uint32_t dst_ = stb_ + arr_*8192 + row_*128 + ((bk_ ^ (row_ & 7))*16);  \
        const void* src_;                                                       \
        if (arr_ == 0)      src_ = Kh_g + (size_t)(k0_ + row_)*DH + bk_*8;      \
        else if (arr_ == 1) src_ = Kl_g + (size_t)(k0_ + row_)*DH + bk_*8;      \
        else                src_ = Vh_g + (size_t)row_*SEQ + k0_ + bk_*8;       \
        cpa16(dst_, src_);                                                      \
    }                                                                           \
    asm volatile("cp.async.commit_group;" ::: "memory");                        \
} while (0)

    AISSUE(0);
    AISSUE(1);

    for (int it = 0; it < 32; it++) {
        if (it < 31) asm volatile("cp.async.wait_group 1;" ::: "memory");
        else         asm volatile("cp.async.wait_group 0;" ::: "memory");
        __syncthreads();
        uint32_t stg = sb + (it & 1)*AT_STG;

        // ---- S = Q K^T (bf16 3-pass, pass-outer)
        float sc[8][4];
#pragma unroll
        for (int nt = 0; nt < 8; nt++)
#pragma unroll
            for (int e = 0; e < 4; e++) sc[nt][e] = 0.f;

#pragma unroll
        for (int kt = 0; kt < 4; kt++) {
            uint32_t kh[4][4], kl[4][4];
#pragma unroll
            for (int nb = 0; nb < 4; nb++) {
                int row = nb*16 + lr8 + (lg >> 1)*8;
                int bk  = 2*kt + (lg & 1);
                uint32_t ad = stg + row*128 + ((bk ^ (row & 7))*16);
                ldsm4(kh[nb], ad);
                ldsm4(kl[nb], ad + 8192);
            }
#pragma unroll
            for (int nb = 0; nb < 4; nb++) {
                mma16816(sc[2*nb],   aqh[kt], kh[nb][0], kh[nb][1]);
                mma16816(sc[2*nb+1], aqh[kt], kh[nb][2], kh[nb][3]);
            }
#pragma unroll
            for (int nb = 0; nb < 4; nb++) {
                mma16816(sc[2*nb],   aqh[kt], kl[nb][0], kl[nb][1]);
                mma16816(sc[2*nb+1], aqh[kt], kl[nb][2], kl[nb][3]);
            }
#pragma unroll
            for (int nb = 0; nb < 4; nb++) {
                mma16816(sc[2*nb],   aql[kt], kh[nb][0], kh[nb][1]);
                mma16816(sc[2*nb+1], aql[kt], kh[nb][2], kh[nb][3]);
            }
        }

        {
            int relb = it*64 + qc - (q0 + r0) + 2047;
            float bb0[9], bb1[9];
#pragma unroll
            for (int t = 0; t < 9; t++) {
                bb0[t] = biasrow[relb - 8 + t*8];
                bb1[t] = biasrow[relb - 7 + t*8];
            }
#pragma unroll
            for (int nt = 0; nt < 8; nt++) {
                sc[nt][0] += bb0[nt+1]; sc[nt][1] += bb1[nt+1];
                sc[nt][2] += bb0[nt];   sc[nt][3] += bb1[nt];
            }
        }

        float mx0 = sc[0][0], mx1 = sc[0][2];
#pragma unroll
        for (int nt = 0; nt < 8; nt++) {
            mx0 = fmaxf(mx0, fmaxf(sc[nt][0], sc[nt][1]));
            mx1 = fmaxf(mx1, fmaxf(sc[nt][2], sc[nt][3]));
        }
        mx0 = fmaxf(mx0, __shfl_xor_sync(0xffffffffu, mx0, 1));
        mx0 = fmaxf(mx0, __shfl_xor_sync(0xffffffffu, mx0, 2));
        mx1 = fmaxf(mx1, __shfl_xor_sync(0xffffffffu, mx1, 1));
        mx1 = fmaxf(mx1, __shfl_xor_sync(0xffffffffu, mx1, 2));
        float m0n = fmaxf(m0, mx0), m1n = fmaxf(m1, mx1);
        float c0 = __expf(m0 - m0n), c1 = __expf(m1 - m1n);
        m0 = m0n; m1 = m1n;
        float s0 = 0.f, s1 = 0.f;
#pragma unroll
        for (int nt = 0; nt < 8; nt++) {
            sc[nt][0] = __expf(sc[nt][0] - m0n);
            sc[nt][1] = __expf(sc[nt][1] - m0n);
            sc[nt][2] = __expf(sc[nt][2] - m1n);
            sc[nt][3] = __expf(sc[nt][3] - m1n);
            s0 += sc[nt][0] + sc[nt][1];
            s1 += sc[nt][2] + sc[nt][3];
        }
        s0 += __shfl_xor_sync(0xffffffffu, s0, 1);
        s0 += __shfl_xor_sync(0xffffffffu, s0, 2);
        s1 += __shfl_xor_sync(0xffffffffu, s1, 1);
        s1 += __shfl_xor_sync(0xffffffffu, s1, 2);
        l0 = l0*c0 + s0; l1 = l1*c1 + s1;
#pragma unroll
        for (int nt = 0; nt < 8; nt++) {
            o[nt][0] *= c0; o[nt][1] *= c0;
            o[nt][2] *= c1; o[nt][3] *= c1;
        }

        // ---- O += P V (fp16 1-pass: P single, V single)
#pragma unroll
        for (int kt = 0; kt < 4; kt++) {
            uint32_t pf[4];
            pf[0] = pkh2(sc[2*kt][0],   sc[2*kt][1]);
            pf[1] = pkh2(sc[2*kt][2],   sc[2*kt][3]);
            pf[2] = pkh2(sc[2*kt+1][0], sc[2*kt+1][1]);
            pf[3] = pkh2(sc[2*kt+1][2], sc[2*kt+1][3]);
            uint32_t vh[4][4];
#pragma unroll
            for (int nb = 0; nb < 4; nb++) {
                int row = nb*16 + lr8 + (lg >> 1)*8;
                int bk  = 2*kt + (lg & 1);
                uint32_t ad = stg + 16384 + row*128 + ((bk ^ (row & 7))*16);
                ldsm4(vh[nb], ad);
            }
#pragma unroll
            for (int nb = 0; nb < 4; nb++) {
                mma16816h(o[2*nb],   pf, vh[nb][0], vh[nb][1]);
                mma16816h(o[2*nb+1], pf, vh[nb][2], vh[nb][3]);
            }
        }
        __syncthreads();
        if (it + 2 < 32) AISSUE(it + 2);
    }

    // normalize + store single fp16 to g_of [b,s,h*64+d]
    float inv0 = 1.0f / l0, inv1 = 1.0f / l1;
    size_t ro0 = ((size_t)b*SEQ + q0 + r0)*DM + h*DH + qc;
    size_t ro1 = ro0 + (size_t)8*DM;
#pragma unroll
    for (int nt = 0; nt < 8; nt++) {
        *(uint32_t*)(g_of + ro0 + nt*8) = pkh2(o[nt][0]*inv0, o[nt][1]*inv0);
        *(uint32_t*)(g_of + ro1 + nt*8) = pkh2(o[nt][2]*inv1, o[nt][3]*inv1);
    }
#undef AISSUE
}

// ---------------- launch -----------------------------------------------------
extern "C" void kernel_launch(void* const* d_in, const int* in_sizes, int n_in,
                              void* d_out, int out_size) {
    const float* X   = (const float*)d_in[0];
    const float* Wq  = (const float*)d_in[1];
    const float* Wk  = (const float*)d_in[2];
    const float* Wv  = (const float*)d_in[3];
    const float* Wo  = (const float*)d_in[4];
    const float* rel = (const float*)d_in[5];
    float* out = (float*)d_out;

    cudaFuncSetAttribute(gemm_mma, cudaFuncAttributeMaxDynamicSharedMemorySize, G_SMEM);
    cudaFuncSetAttribute(attn_mma, cudaFuncAttributeMaxDynamicSharedMemorySize, 2*AT_STG);

    bias_kernel<<<16, 256>>>(rel);
    conv_split<<<4096, 256>>>((const float4*)X);
    conv_wT<<<dim3(32, 32, 4), dim3(32, 8)>>>(Wq, Wk, Wv, Wo);

    gemm_mma<<<dim3(24, 32), 256, G_SMEM>>>(1, nullptr);   // fused QKV (bf16 3-pass)

    attn_mma<<<dim3(SEQ/64, BATCH*NH), 128, 2*AT_STG>>>();

    gemm_mma<<<dim3(8, 32), 256, G_SMEM>>>(0, out);        // O proj (fp16 2-pass)
}